// round 7
// baseline (speedup 1.0000x reference)
#include <cuda_runtime.h>
#include <cuda_bf16.h>
#include <math.h>
#include <stdint.h>

// ----------------------------------------------------------------------------
// Problem constants
// ----------------------------------------------------------------------------
#define BATCH   2
#define SEQ     2048
#define TOK     (BATCH * SEQ)        // 4096 rows
#define DMODEL  1024
#define DFF     4096
#define NHEADS  16
#define HDIM    64                   // head dim
#define LN_EPS  1e-5f

// ----------------------------------------------------------------------------
// Scratch buffers (static device allocations; no cudaMalloc allowed)
// ----------------------------------------------------------------------------
__device__ float g_q   [TOK * DMODEL];
__device__ float g_k   [TOK * DMODEL];
__device__ float g_v   [TOK * DMODEL];
__device__ float g_attn[TOK * DMODEL];
__device__ float g_tmp [TOK * DMODEL];
__device__ float g_y1  [TOK * DMODEL];
__device__ float g_y2  [TOK * DMODEL];
__device__ float g_ffn [TOK * DFF];

__device__ __forceinline__ float f2tf32(float x) {
    uint32_t r;
    asm("cvt.rna.tf32.f32 %0, %1;" : "=r"(r) : "f"(x));
    return __uint_as_float(r);
}
__device__ __forceinline__ uint32_t tf32r(float x) {
    uint32_t r;
    asm("cvt.rna.tf32.f32 %0, %1;" : "=r"(r) : "f"(x));
    return r;
}

#define MMA_TF32(acc, a, b0v, b1v)                                         \
    asm volatile(                                                          \
        "mma.sync.aligned.m16n8k8.row.col.f32.tf32.tf32.f32 "              \
        "{%0,%1,%2,%3}, {%4,%5,%6,%7}, {%8,%9}, {%0,%1,%2,%3};"            \
        : "+f"((acc)[0]), "+f"((acc)[1]), "+f"((acc)[2]), "+f"((acc)[3])   \
        : "r"((a)[0]), "r"((a)[1]), "r"((a)[2]), "r"((a)[3]),              \
          "r"(b0v), "r"(b1v))

__device__ __forceinline__ void cp_async16(uint32_t smem, const void* gptr) {
    asm volatile("cp.async.cg.shared.global [%0], [%1], 16;"
                 :: "r"(smem), "l"(gptr));
}
#define CP_COMMIT() asm volatile("cp.async.commit_group;")
#define CP_WAIT(n)  asm volatile("cp.async.wait_group %0;" :: "n"(n))

__device__ __forceinline__ uint32_t smem_u32(const void* p) {
    return (uint32_t)__cvta_generic_to_shared(p);
}

// ----------------------------------------------------------------------------
// tf32 tensor-core GEMM, 4-stage cp.async pipeline.
//   C[M,N] = A[M,K] @ W[K,N] + bias[N] (+ R) (optional ReLU)
//   BM=BN=128, BK=16, 256 threads (8 warps as 2x4), warp tile 64x32.
//   tf32 rounding (cvt.rna) applied on fragments in registers.
// ----------------------------------------------------------------------------
struct GemmArgs {
    const float* A[3];
    const float* W[3];
    const float* bias[3];
    const float* R[3];
    float*       C[3];
    int N, K;
};

#define AS_STRIDE 20     // words per A row (16 + 4 pad), conflict-free frags
#define BS_STRIDE 136    // words per B row (128 + 8 pad), conflict-free frags
#define STAGES 4
#define A_STG (128 * AS_STRIDE)          // words per A stage
#define B_STG (16  * BS_STRIDE)          // words per B stage
#define GEMM_SMEM (STAGES * (A_STG + B_STG) * 4)   // bytes (≈74 KB)

template<bool RELU, bool RES>
__global__ __launch_bounds__(256, 2) void gemm_tf32(GemmArgs args)
{
    extern __shared__ float smx[];
    float* Abuf = smx;                       // [STAGES][A_STG]
    float* Bbuf = smx + STAGES * A_STG;      // [STAGES][B_STG]

    const int zi = blockIdx.z;
    const float* __restrict__ A    = args.A[zi];
    const float* __restrict__ W    = args.W[zi];
    const float* __restrict__ bias = args.bias[zi];
    const float* __restrict__ Rp   = args.R[zi];
    float*       __restrict__ C    = args.C[zi];
    const int N = args.N, K = args.K;

    const int tid  = threadIdx.x;
    const int lane = tid & 31;
    const int warp = tid >> 5;
    const int g    = lane >> 2;
    const int tg   = lane & 3;
    const int wm   = (warp >> 2) * 64;
    const int wn   = (warp & 3) * 32;
    const int bm   = blockIdx.y * 128;
    const int bn   = blockIdx.x * 128;

    // cp.async mapping: A tile 128x16 -> 512 float4, 2/thread
    const int a_r0 = tid >> 2;               // rows tid>>2 and +64? no: idx scheme below
    // idx = tid + i*256 ; row = idx>>2 (0..127), c4 = (idx&3)*4
    // B tile 16x128 -> 512 float4, 2/thread: row = idx>>5 (0..15), c4=(idx&31)*4
    const int a_row0 = (tid + 0)   >> 2, a_c40 = ((tid + 0)   & 3) * 4;
    const int a_row1 = (tid + 256) >> 2, a_c41 = ((tid + 256) & 3) * 4;
    const int b_row0 = (tid + 0)   >> 5, b_c40 = ((tid + 0)   & 31) * 4;
    const int b_row1 = (tid + 256) >> 5, b_c41 = ((tid + 256) & 31) * 4;

    const uint32_t sA = smem_u32(Abuf);
    const uint32_t sB = smem_u32(Bbuf);

#define ISSUE(t) do {                                                         \
        const int st = (t) % STAGES;                                          \
        const uint32_t sa = sA + (uint32_t)(st * A_STG) * 4;                  \
        const uint32_t sb = sB + (uint32_t)(st * B_STG) * 4;                  \
        const size_t ka = (size_t)(t) * 16;                                   \
        cp_async16(sa + (a_row0 * AS_STRIDE + a_c40) * 4,                     \
                   A + (size_t)(bm + a_row0) * K + ka + a_c40);               \
        cp_async16(sa + (a_row1 * AS_STRIDE + a_c41) * 4,                     \
                   A + (size_t)(bm + a_row1) * K + ka + a_c41);               \
        cp_async16(sb + (b_row0 * BS_STRIDE + b_c40) * 4,                     \
                   W + (ka + b_row0) * (size_t)N + bn + b_c40);               \
        cp_async16(sb + (b_row1 * BS_STRIDE + b_c41) * 4,                     \
                   W + (ka + b_row1) * (size_t)N + bn + b_c41);               \
        CP_COMMIT();                                                          \
    } while (0)

    float acc[4][4][4];
#pragma unroll
    for (int i = 0; i < 4; i++)
#pragma unroll
        for (int j = 0; j < 4; j++)
#pragma unroll
            for (int r = 0; r < 4; r++) acc[i][j][r] = 0.f;

    const int NT = K >> 4;

    ISSUE(0); ISSUE(1); ISSUE(2);

    for (int t = 0; t < NT; t++) {
        CP_WAIT(2);            // stage t landed
        __syncthreads();       // visible to all warps; prior readers done

        const float* as_ = Abuf + (t % STAGES) * A_STG;
        const float* bs_ = Bbuf + (t % STAGES) * B_STG;
#pragma unroll
        for (int kk = 0; kk < 16; kk += 8) {
            unsigned af[4][4], bf[4][2];
#pragma unroll
            for (int mt = 0; mt < 4; mt++) {
                const float* ap = as_ + (wm + mt * 16 + g) * AS_STRIDE + kk + tg;
                af[mt][0] = tf32r(ap[0]);
                af[mt][1] = tf32r(ap[8 * AS_STRIDE]);
                af[mt][2] = tf32r(ap[4]);
                af[mt][3] = tf32r(ap[8 * AS_STRIDE + 4]);
            }
#pragma unroll
            for (int nt = 0; nt < 4; nt++) {
                const float* bp = bs_ + (kk + tg) * BS_STRIDE + wn + nt * 8 + g;
                bf[nt][0] = tf32r(bp[0]);
                bf[nt][1] = tf32r(bp[4 * BS_STRIDE]);
            }
#pragma unroll
            for (int mt = 0; mt < 4; mt++)
#pragma unroll
                for (int nt = 0; nt < 4; nt++)
                    MMA_TF32(acc[mt][nt], af[mt], bf[nt][0], bf[nt][1]);
        }

        if (t + STAGES - 1 < NT) {
            __syncthreads();   // all reads of buffer (t+3)%4 (= tile t-1) done
            ISSUE(t + STAGES - 1);
        }
    }

    // epilogue: C-fragment rows = g, g+8 ; cols = 2*tg, 2*tg+1
#pragma unroll
    for (int mt = 0; mt < 4; mt++) {
        const int row0 = bm + wm + mt * 16 + g;
#pragma unroll
        for (int nt = 0; nt < 4; nt++) {
            const int col = bn + wn + nt * 8 + tg * 2;
            const float bv0 = bias[col], bv1 = bias[col + 1];
            float2 v0, v1;
            v0.x = acc[mt][nt][0] + bv0; v0.y = acc[mt][nt][1] + bv1;
            v1.x = acc[mt][nt][2] + bv0; v1.y = acc[mt][nt][3] + bv1;
            if (RES) {
                float2 r0 = *(const float2*)(Rp + (size_t)row0 * N + col);
                float2 r1 = *(const float2*)(Rp + (size_t)(row0 + 8) * N + col);
                v0.x += r0.x; v0.y += r0.y;
                v1.x += r1.x; v1.y += r1.y;
            }
            if (RELU) {
                v0.x = fmaxf(v0.x, 0.f); v0.y = fmaxf(v0.y, 0.f);
                v1.x = fmaxf(v1.x, 0.f); v1.y = fmaxf(v1.y, 0.f);
            }
            *(float2*)(C + (size_t)row0 * N + col)       = v0;
            *(float2*)(C + (size_t)(row0 + 8) * N + col) = v1;
        }
    }
#undef ISSUE
}

// ----------------------------------------------------------------------------
// Tensor-core flash attention (tf32 mma) — unchanged from R6 pass.
// ----------------------------------------------------------------------------
#define ASTR 72
#define ATT_SMEM (256 * ASTR * 4)

template<bool CAUSAL>
__global__ __launch_bounds__(128) void attn_tc(
    const float* __restrict__ Q, const float* __restrict__ K,
    const float* __restrict__ V, float* __restrict__ O)
{
    extern __shared__ float sm[];
    float* sQ = sm;
    float* sK = sm + 64 * ASTR;
    float* sV = sm + 128 * ASTR;
    float* sP = sm + 192 * ASTR;

    const int b  = blockIdx.z;
    const int h  = blockIdx.y;
    const int q0 = blockIdx.x * 64;
    const int tid  = threadIdx.x;
    const int lane = tid & 31;
    const int w    = tid >> 5;
    const int g    = lane >> 2;
    const int tg   = lane & 3;
    const size_t hoff = ((size_t)(b * NHEADS + h)) * SEQ * HDIM;

#pragma unroll
    for (int i = 0; i < 8; i++) {
        const int idx = tid + i * 128;
        const int row = idx >> 4;
        const int c4  = (idx & 15) << 2;
        float4 t = *(const float4*)(Q + hoff + (size_t)(q0 + row) * HDIM + c4);
        float4 o;
        o.x = f2tf32(t.x * 0.125f); o.y = f2tf32(t.y * 0.125f);
        o.z = f2tf32(t.z * 0.125f); o.w = f2tf32(t.w * 0.125f);
        *(float4*)(sQ + row * ASTR + c4) = o;
    }
    __syncthreads();

    unsigned aQ[8][4];
    {
        const float* qb = sQ + (w * 16 + g) * ASTR;
#pragma unroll
        for (int kk = 0; kk < 8; kk++) {
            aQ[kk][0] = __float_as_uint(qb[kk * 8 + tg]);
            aQ[kk][1] = __float_as_uint(qb[8 * ASTR + kk * 8 + tg]);
            aQ[kk][2] = __float_as_uint(qb[kk * 8 + tg + 4]);
            aQ[kk][3] = __float_as_uint(qb[8 * ASTR + kk * 8 + tg + 4]);
        }
    }

    float cO[8][4];
#pragma unroll
    for (int nt = 0; nt < 8; nt++)
#pragma unroll
        for (int r = 0; r < 4; r++) cO[nt][r] = 0.f;
    float mrow[2] = { -1e30f, -1e30f };
    float lrow[2] = { 0.f, 0.f };

    const int ntiles = CAUSAL ? (q0 / 64 + 1) : (SEQ / 64);

    for (int t = 0; t < ntiles; t++) {
        const int j0 = t * 64;
        __syncthreads();
#pragma unroll
        for (int i = 0; i < 8; i++) {
            const int idx = tid + i * 128;
            const int row = idx >> 4;
            const int c4  = (idx & 15) << 2;
            const size_t gaddr = hoff + (size_t)(j0 + row) * HDIM + c4;
            float4 kt = *(const float4*)(K + gaddr);
            float4 ko;
            ko.x = f2tf32(kt.x); ko.y = f2tf32(kt.y);
            ko.z = f2tf32(kt.z); ko.w = f2tf32(kt.w);
            *(float4*)(sK + row * ASTR + c4) = ko;
            float4 vt = *(const float4*)(V + gaddr);
            float4 vo;
            vo.x = f2tf32(vt.x); vo.y = f2tf32(vt.y);
            vo.z = f2tf32(vt.z); vo.w = f2tf32(vt.w);
            *(float4*)(sV + row * ASTR + c4) = vo;
        }
        __syncthreads();

        float cS[8][4];
#pragma unroll
        for (int nt = 0; nt < 8; nt++)
#pragma unroll
            for (int r = 0; r < 4; r++) cS[nt][r] = 0.f;

#pragma unroll
        for (int kk = 0; kk < 8; kk++)
#pragma unroll
            for (int nt = 0; nt < 8; nt++) {
                const float* kp = sK + (nt * 8 + g) * ASTR + kk * 8 + tg;
                unsigned b0 = __float_as_uint(kp[0]);
                unsigned b1 = __float_as_uint(kp[4]);
                MMA_TF32(cS[nt], aQ[kk], b0, b1);
            }

        if (CAUSAL && t == ntiles - 1) {
            const int rbase = q0 + w * 16 + g;
#pragma unroll
            for (int nt = 0; nt < 8; nt++) {
                const int c0 = j0 + nt * 8 + tg * 2;
                if (c0     > rbase)     cS[nt][0] = -1e30f;
                if (c0 + 1 > rbase)     cS[nt][1] = -1e30f;
                if (c0     > rbase + 8) cS[nt][2] = -1e30f;
                if (c0 + 1 > rbase + 8) cS[nt][3] = -1e30f;
            }
        }

        float* pb = sP + (w * 16) * ASTR;
#pragma unroll
        for (int rh = 0; rh < 2; rh++) {
            float mx = -1e30f;
#pragma unroll
            for (int nt = 0; nt < 8; nt++)
                mx = fmaxf(mx, fmaxf(cS[nt][2 * rh], cS[nt][2 * rh + 1]));
            mx = fmaxf(mx, __shfl_xor_sync(0xffffffffu, mx, 1));
            mx = fmaxf(mx, __shfl_xor_sync(0xffffffffu, mx, 2));
            const float mnew = fmaxf(mrow[rh], mx);
            const float corr = __expf(mrow[rh] - mnew);
            float sum = 0.f;
#pragma unroll
            for (int nt = 0; nt < 8; nt++) {
                float p0 = __expf(cS[nt][2 * rh]     - mnew);
                float p1 = __expf(cS[nt][2 * rh + 1] - mnew);
                cS[nt][2 * rh]     = p0;
                cS[nt][2 * rh + 1] = p1;
                sum += p0 + p1;
            }
            sum += __shfl_xor_sync(0xffffffffu, sum, 1);
            sum += __shfl_xor_sync(0xffffffffu, sum, 2);
            lrow[rh] = lrow[rh] * corr + sum;
            mrow[rh] = mnew;
#pragma unroll
            for (int nt = 0; nt < 8; nt++) {
                cO[nt][2 * rh]     *= corr;
                cO[nt][2 * rh + 1] *= corr;
            }
            float* prow = pb + (g + 8 * rh) * ASTR;
#pragma unroll
            for (int nt = 0; nt < 8; nt++) {
                float2 pv;
                pv.x = f2tf32(cS[nt][2 * rh]);
                pv.y = f2tf32(cS[nt][2 * rh + 1]);
                *(float2*)(prow + nt * 8 + tg * 2) = pv;
            }
        }
        __syncwarp();

#pragma unroll
        for (int kk = 0; kk < 8; kk++) {
            unsigned aP[4];
            aP[0] = __float_as_uint(pb[g * ASTR + kk * 8 + tg]);
            aP[1] = __float_as_uint(pb[(g + 8) * ASTR + kk * 8 + tg]);
            aP[2] = __float_as_uint(pb[g * ASTR + kk * 8 + tg + 4]);
            aP[3] = __float_as_uint(pb[(g + 8) * ASTR + kk * 8 + tg + 4]);
#pragma unroll
            for (int nt = 0; nt < 8; nt++) {
                const float* vp0 = sV + (kk * 8 + tg) * ASTR + nt * 8 + g;
                const float* vp1 = sV + (kk * 8 + tg + 4) * ASTR + nt * 8 + g;
                unsigned b0 = __float_as_uint(vp0[0]);
                unsigned b1 = __float_as_uint(vp1[0]);
                MMA_TF32(cO[nt], aP, b0, b1);
            }
        }
    }

    const float inv0 = 1.f / lrow[0];
    const float inv1 = 1.f / lrow[1];
    const int r0 = q0 + w * 16 + g;
    float* o0p = O + (size_t)(b * SEQ + r0) * DMODEL + h * HDIM;
    float* o1p = O + (size_t)(b * SEQ + r0 + 8) * DMODEL + h * HDIM;
#pragma unroll
    for (int nt = 0; nt < 8; nt++) {
        const int c = nt * 8 + tg * 2;
        float2 v0, v1;
        v0.x = cO[nt][0] * inv0; v0.y = cO[nt][1] * inv0;
        v1.x = cO[nt][2] * inv1; v1.y = cO[nt][3] * inv1;
        *(float2*)(o0p + c) = v0;
        *(float2*)(o1p + c) = v1;
    }
}

// ----------------------------------------------------------------------------
// LayerNorm (unchanged)
// ----------------------------------------------------------------------------
__global__ __launch_bounds__(256) void ln_kernel(
    const float* __restrict__ X, const float* __restrict__ g,
    const float* __restrict__ bb, float* __restrict__ Y)
{
    __shared__ float red[16];
    const int row = blockIdx.x;
    const int tid = threadIdx.x;
    const float4 xv = *(const float4*)(X + (size_t)row * DMODEL + tid * 4);

    float s  = xv.x + xv.y + xv.z + xv.w;
    float sq = xv.x*xv.x + xv.y*xv.y + xv.z*xv.z + xv.w*xv.w;
#pragma unroll
    for (int off = 16; off > 0; off >>= 1) {
        s  += __shfl_xor_sync(0xffffffffu, s,  off);
        sq += __shfl_xor_sync(0xffffffffu, sq, off);
    }
    const int warp = tid >> 5, lane = tid & 31;
    if (lane == 0) { red[warp] = s; red[warp + 8] = sq; }
    __syncthreads();
    if (warp == 0) {
        float a = (lane < 8) ? red[lane] : 0.f;
        float c = (lane < 8) ? red[lane + 8] : 0.f;
#pragma unroll
        for (int off = 4; off > 0; off >>= 1) {
            a += __shfl_xor_sync(0xffffffffu, a, off);
            c += __shfl_xor_sync(0xffffffffu, c, off);
        }
        if (lane == 0) { red[0] = a; red[1] = c; }
    }
    __syncthreads();
    const float mu  = red[0] * (1.f / DMODEL);
    const float var = red[1] * (1.f / DMODEL) - mu * mu;
    const float rstd = rsqrtf(var + LN_EPS);

    const float4 gv = *(const float4*)(g  + tid * 4);
    const float4 bv = *(const float4*)(bb + tid * 4);
    float4 yv;
    yv.x = (xv.x - mu) * rstd * gv.x + bv.x;
    yv.y = (xv.y - mu) * rstd * gv.y + bv.y;
    yv.z = (xv.z - mu) * rstd * gv.z + bv.z;
    yv.w = (xv.w - mu) * rstd * gv.w + bv.w;
    *(float4*)(Y + (size_t)row * DMODEL + tid * 4) = yv;
}

// ----------------------------------------------------------------------------
// Launch
// ----------------------------------------------------------------------------
extern "C" void kernel_launch(void* const* d_in, const int* in_sizes, int n_in,
                              void* d_out, int out_size)
{
    const float* x    = (const float*)d_in[0];
    const float* enc  = (const float*)d_in[1];
    const float* s_wq = (const float*)d_in[2];  const float* s_bq = (const float*)d_in[3];
    const float* s_wk = (const float*)d_in[4];  const float* s_bk = (const float*)d_in[5];
    const float* s_wv = (const float*)d_in[6];  const float* s_bv = (const float*)d_in[7];
    const float* s_wo = (const float*)d_in[8];  const float* s_bo = (const float*)d_in[9];
    const float* c_wq = (const float*)d_in[10]; const float* c_bq = (const float*)d_in[11];
    const float* c_wk = (const float*)d_in[12]; const float* c_bk = (const float*)d_in[13];
    const float* c_wv = (const float*)d_in[14]; const float* c_bv = (const float*)d_in[15];
    const float* c_wo = (const float*)d_in[16]; const float* c_bo = (const float*)d_in[17];
    const float* f_w1 = (const float*)d_in[18]; const float* f_b1 = (const float*)d_in[19];
    const float* f_w2 = (const float*)d_in[20]; const float* f_b2 = (const float*)d_in[21];
    const float* ln1g = (const float*)d_in[22]; const float* ln1b = (const float*)d_in[23];
    const float* ln2g = (const float*)d_in[24]; const float* ln2b = (const float*)d_in[25];
    const float* ln3g = (const float*)d_in[26]; const float* ln3b = (const float*)d_in[27];
    float* out = (float*)d_out;

    float *q, *k, *v, *attn, *tmp, *y1, *y2, *ffn;
    cudaGetSymbolAddress((void**)&q,    g_q);
    cudaGetSymbolAddress((void**)&k,    g_k);
    cudaGetSymbolAddress((void**)&v,    g_v);
    cudaGetSymbolAddress((void**)&attn, g_attn);
    cudaGetSymbolAddress((void**)&tmp,  g_tmp);
    cudaGetSymbolAddress((void**)&y1,   g_y1);
    cudaGetSymbolAddress((void**)&y2,   g_y2);
    cudaGetSymbolAddress((void**)&ffn,  g_ffn);

    cudaFuncSetAttribute(gemm_tf32<false,false>,
        cudaFuncAttributeMaxDynamicSharedMemorySize, GEMM_SMEM);
    cudaFuncSetAttribute(gemm_tf32<false,true>,
        cudaFuncAttributeMaxDynamicSharedMemorySize, GEMM_SMEM);
    cudaFuncSetAttribute(gemm_tf32<true,false>,
        cudaFuncAttributeMaxDynamicSharedMemorySize, GEMM_SMEM);
    cudaFuncSetAttribute(attn_tc<true>,
        cudaFuncAttributeMaxDynamicSharedMemorySize, ATT_SMEM);
    cudaFuncSetAttribute(attn_tc<false>,
        cudaFuncAttributeMaxDynamicSharedMemorySize, ATT_SMEM);

    const dim3 blk(256);
    const dim3 ablk(128);
    const dim3 gatt(SEQ / 64, NHEADS, BATCH);
    const dim3 gln(TOK);

    GemmArgs ga;

    // ---- self attention: fused QKV projection (z=3) ----
    ga = GemmArgs{};
    ga.A[0] = x;    ga.A[1] = x;    ga.A[2] = x;
    ga.W[0] = s_wq; ga.W[1] = s_wk; ga.W[2] = s_wv;
    ga.bias[0] = s_bq; ga.bias[1] = s_bk; ga.bias[2] = s_bv;
    ga.R[0] = x; ga.R[1] = x; ga.R[2] = x;
    ga.C[0] = q; ga.C[1] = k; ga.C[2] = v;
    ga.N = DMODEL; ga.K = DMODEL;
    gemm_tf32<false,false><<<dim3(DMODEL/128, TOK/128, 3), blk, GEMM_SMEM>>>(ga);

    attn_tc<true><<<gatt, ablk, ATT_SMEM>>>(q, k, v, attn);

    ga.A[0] = attn; ga.W[0] = s_wo; ga.bias[0] = s_bo; ga.R[0] = x; ga.C[0] = tmp;
    gemm_tf32<false,true><<<dim3(DMODEL/128, TOK/128, 1), blk, GEMM_SMEM>>>(ga);
    ln_kernel<<<gln, blk>>>(tmp, ln1g, ln1b, y1);

    // ---- cross attention: fused Q(y1) + K,V(enc) projection (z=3) ----
    ga.A[0] = y1;   ga.A[1] = enc;  ga.A[2] = enc;
    ga.W[0] = c_wq; ga.W[1] = c_wk; ga.W[2] = c_wv;
    ga.bias[0] = c_bq; ga.bias[1] = c_bk; ga.bias[2] = c_bv;
    ga.R[0] = x; ga.R[1] = x; ga.R[2] = x;
    ga.C[0] = q; ga.C[1] = k; ga.C[2] = v;
    gemm_tf32<false,false><<<dim3(DMODEL/128, TOK/128, 3), blk, GEMM_SMEM>>>(ga);

    attn_tc<false><<<gatt, ablk, ATT_SMEM>>>(q, k, v, attn);

    ga.A[0] = attn; ga.W[0] = c_wo; ga.bias[0] = c_bo; ga.R[0] = y1; ga.C[0] = tmp;
    gemm_tf32<false,true><<<dim3(DMODEL/128, TOK/128, 1), blk, GEMM_SMEM>>>(ga);
    ln_kernel<<<gln, blk>>>(tmp, ln2g, ln2b, y2);

    // ---- FFN ----
    ga.A[0] = y2; ga.W[0] = f_w1; ga.bias[0] = f_b1; ga.R[0] = x; ga.C[0] = ffn;
    ga.N = DFF; ga.K = DMODEL;
    gemm_tf32<true,false><<<dim3(DFF/128, TOK/128, 1), blk, GEMM_SMEM>>>(ga);

    ga.A[0] = ffn; ga.W[0] = f_w2; ga.bias[0] = f_b2; ga.R[0] = y2; ga.C[0] = tmp;
    ga.N = DMODEL; ga.K = DFF;
    gemm_tf32<false,true><<<dim3(DMODEL/128, TOK/128, 1), blk, GEMM_SMEM>>>(ga);
    ln_kernel<<<gln, blk>>>(tmp, ln3g, ln3b, out);
}

// round 8
// speedup vs baseline: 1.3118x; 1.3118x over previous
#include <cuda_runtime.h>
#include <cuda_bf16.h>
#include <math.h>
#include <stdint.h>

// ----------------------------------------------------------------------------
// Problem constants
// ----------------------------------------------------------------------------
#define BATCH   2
#define SEQ     2048
#define TOK     (BATCH * SEQ)        // 4096 rows
#define DMODEL  1024
#define DFF     4096
#define NHEADS  16
#define HDIM    64                   // head dim
#define LN_EPS  1e-5f

// ----------------------------------------------------------------------------
// Scratch buffers
// ----------------------------------------------------------------------------
__device__ float g_q   [TOK * DMODEL];
__device__ float g_k   [TOK * DMODEL];
__device__ float g_v   [TOK * DMODEL];
__device__ float g_attn[TOK * DMODEL];
__device__ float g_tmp [TOK * DMODEL];
__device__ float g_y1  [TOK * DMODEL];
__device__ float g_y2  [TOK * DMODEL];
__device__ float g_ffn [TOK * DFF];

__device__ __forceinline__ float f2tf32(float x) {
    uint32_t r;
    asm("cvt.rna.tf32.f32 %0, %1;" : "=r"(r) : "f"(x));
    return __uint_as_float(r);
}

// pack two fp32 -> bf16x2 word: low half = lo, high half = hi
__device__ __forceinline__ uint32_t packbf(float lo, float hi) {
    uint32_t d;
    asm("cvt.rn.bf16x2.f32 %0, %1, %2;" : "=r"(d) : "f"(hi), "f"(lo));
    return d;
}

#define MMA_TF32(acc, a, b0v, b1v)                                         \
    asm volatile(                                                          \
        "mma.sync.aligned.m16n8k8.row.col.f32.tf32.tf32.f32 "              \
        "{%0,%1,%2,%3}, {%4,%5,%6,%7}, {%8,%9}, {%0,%1,%2,%3};"            \
        : "+f"((acc)[0]), "+f"((acc)[1]), "+f"((acc)[2]), "+f"((acc)[3])   \
        : "r"((a)[0]), "r"((a)[1]), "r"((a)[2]), "r"((a)[3]),              \
          "r"(b0v), "r"(b1v))

#define MMA_BF16(acc, a, b0v, b1v)                                         \
    asm volatile(                                                          \
        "mma.sync.aligned.m16n8k16.row.col.f32.bf16.bf16.f32 "             \
        "{%0,%1,%2,%3}, {%4,%5,%6,%7}, {%8,%9}, {%0,%1,%2,%3};"            \
        : "+f"((acc)[0]), "+f"((acc)[1]), "+f"((acc)[2]), "+f"((acc)[3])   \
        : "r"((a)[0]), "r"((a)[1]), "r"((a)[2]), "r"((a)[3]),              \
          "r"(b0v), "r"(b1v))

// ----------------------------------------------------------------------------
// bf16 tensor-core GEMM, register double-buffered (R6 structure).
//   C[M,N] = A[M,K] @ W[K,N] + bias[N] (+ R) (optional ReLU)
//   BM=BN=128, BK=16, 256 threads (8 warps as 2x4), warp tile 64x32.
//   fp32 inputs converted to bf16 at smem staging; fp32 accumulate.
//   A smem: [128 rows][8 words] packed bf16x2 along K, stride 12 words.
//   B smem: [8 kpair rows][128 cols] words = {k even, k odd}, stride 136.
// ----------------------------------------------------------------------------
struct GemmArgs {
    const float* A[3];
    const float* W[3];
    const float* bias[3];
    const float* R[3];
    float*       C[3];
    int N, K;
};

#define A_WSTR 12     // words per A row (8 + 4 pad) -> conflict-free
#define B_WSTR 136    // words per B kpair row (128 + 8 pad) -> conflict-free
#define A_WRDS (128 * A_WSTR)
#define B_WRDS (8 * B_WSTR)

template<bool RELU, bool RES>
__global__ __launch_bounds__(256, 2) void gemm_bf16(GemmArgs args)
{
    __shared__ uint32_t As[2][A_WRDS];
    __shared__ uint32_t Bs[2][B_WRDS];

    const int zi = blockIdx.z;
    const float* __restrict__ A    = args.A[zi];
    const float* __restrict__ W    = args.W[zi];
    const float* __restrict__ bias = args.bias[zi];
    const float* __restrict__ Rp   = args.R[zi];
    float*       __restrict__ C    = args.C[zi];
    const int N = args.N, K = args.K;

    const int tid  = threadIdx.x;
    const int lane = tid & 31;
    const int warp = tid >> 5;
    const int g    = lane >> 2;
    const int tg   = lane & 3;
    const int wm   = (warp >> 2) * 64;
    const int wn   = (warp & 3) * 32;
    const int bm   = blockIdx.y * 128;
    const int bn   = blockIdx.x * 128;

    // A global: idx = tid and tid+256 -> rows tid>>2 and +64, cols (tid&3)*4
    const int a_row = tid >> 2;           // 0..63
    const int a_c4  = (tid & 3) * 4;      // 0..12
    // B global: thread owns kpair p = tid>>5, word-cols (tid&31)*4..+3
    const int b_p   = tid >> 5;           // 0..7
    const int b_c4  = (tid & 31) * 4;     // 0..124

    const float* Ag0 = A + (size_t)(bm + a_row)      * K + a_c4;
    const float* Ag1 = A + (size_t)(bm + a_row + 64) * K + a_c4;
    const float* Wg0 = W + (size_t)(2 * b_p)     * N + bn + b_c4;
    const float* Wg1 = W + (size_t)(2 * b_p + 1) * N + bn + b_c4;

    float acc[4][4][4];
#pragma unroll
    for (int i = 0; i < 4; i++)
#pragma unroll
        for (int j = 0; j < 4; j++)
#pragma unroll
            for (int r = 0; r < 4; r++) acc[i][j][r] = 0.f;

    float4 ra0, ra1, rb0, rb1;

#define LOADG(t) do {                                                \
        const size_t ka = (size_t)(t) * 16;                          \
        const size_t kb = (size_t)(t) * 16 * (size_t)N;              \
        ra0 = *(const float4*)(Ag0 + ka);                            \
        ra1 = *(const float4*)(Ag1 + ka);                            \
        rb0 = *(const float4*)(Wg0 + kb);                            \
        rb1 = *(const float4*)(Wg1 + kb);                            \
    } while (0)

#define STORES(buf) do {                                             \
        uint32_t* as_ = As[buf];                                     \
        uint32_t* bs_ = Bs[buf];                                     \
        uint2 aw0, aw1;                                              \
        aw0.x = packbf(ra0.x, ra0.y); aw0.y = packbf(ra0.z, ra0.w);  \
        aw1.x = packbf(ra1.x, ra1.y); aw1.y = packbf(ra1.z, ra1.w);  \
        *(uint2*)(as_ + a_row * A_WSTR + (a_c4 >> 1)) = aw0;         \
        *(uint2*)(as_ + (a_row + 64) * A_WSTR + (a_c4 >> 1)) = aw1;  \
        uint4 bw;                                                    \
        bw.x = packbf(rb0.x, rb1.x); bw.y = packbf(rb0.y, rb1.y);    \
        bw.z = packbf(rb0.z, rb1.z); bw.w = packbf(rb0.w, rb1.w);    \
        *(uint4*)(bs_ + b_p * B_WSTR + b_c4) = bw;                   \
    } while (0)

    const int NT = K >> 4;

    LOADG(0);
    STORES(0);
    __syncthreads();

    for (int t = 0; t < NT; t++) {
        const int cur = t & 1;
        if (t + 1 < NT) LOADG(t + 1);

        const uint32_t* as_ = As[cur];
        const uint32_t* bs_ = Bs[cur];

        unsigned af[4][4], bf2[4][2];
#pragma unroll
        for (int mt = 0; mt < 4; mt++) {
            const uint32_t* ap = as_ + (wm + mt * 16 + g) * A_WSTR + tg;
            af[mt][0] = ap[0];
            af[mt][1] = ap[8 * A_WSTR];
            af[mt][2] = ap[4];
            af[mt][3] = ap[8 * A_WSTR + 4];
        }
#pragma unroll
        for (int nt = 0; nt < 4; nt++) {
            const int col = wn + nt * 8 + g;
            bf2[nt][0] = bs_[tg * B_WSTR + col];
            bf2[nt][1] = bs_[(tg + 4) * B_WSTR + col];
        }
#pragma unroll
        for (int mt = 0; mt < 4; mt++)
#pragma unroll
            for (int nt = 0; nt < 4; nt++)
                MMA_BF16(acc[mt][nt], af[mt], bf2[nt][0], bf2[nt][1]);

        if (t + 1 < NT) STORES((t + 1) & 1);
        __syncthreads();
    }

    // epilogue: C-fragment rows = g, g+8 ; cols = 2*tg, 2*tg+1
#pragma unroll
    for (int mt = 0; mt < 4; mt++) {
        const int row0 = bm + wm + mt * 16 + g;
#pragma unroll
        for (int nt = 0; nt < 4; nt++) {
            const int col = bn + wn + nt * 8 + tg * 2;
            const float bv0 = bias[col], bv1 = bias[col + 1];
            float2 v0, v1;
            v0.x = acc[mt][nt][0] + bv0; v0.y = acc[mt][nt][1] + bv1;
            v1.x = acc[mt][nt][2] + bv0; v1.y = acc[mt][nt][3] + bv1;
            if (RES) {
                float2 r0 = *(const float2*)(Rp + (size_t)row0 * N + col);
                float2 r1 = *(const float2*)(Rp + (size_t)(row0 + 8) * N + col);
                v0.x += r0.x; v0.y += r0.y;
                v1.x += r1.x; v1.y += r1.y;
            }
            if (RELU) {
                v0.x = fmaxf(v0.x, 0.f); v0.y = fmaxf(v0.y, 0.f);
                v1.x = fmaxf(v1.x, 0.f); v1.y = fmaxf(v1.y, 0.f);
            }
            *(float2*)(C + (size_t)row0 * N + col)       = v0;
            *(float2*)(C + (size_t)(row0 + 8) * N + col) = v1;
        }
    }
#undef LOADG
#undef STORES
}

// ----------------------------------------------------------------------------
// Tensor-core flash attention (tf32 mma) — unchanged from R6 pass.
// ----------------------------------------------------------------------------
#define ASTR 72
#define ATT_SMEM (256 * ASTR * 4)

template<bool CAUSAL>
__global__ __launch_bounds__(128) void attn_tc(
    const float* __restrict__ Q, const float* __restrict__ K,
    const float* __restrict__ V, float* __restrict__ O)
{
    extern __shared__ float sm[];
    float* sQ = sm;
    float* sK = sm + 64 * ASTR;
    float* sV = sm + 128 * ASTR;
    float* sP = sm + 192 * ASTR;

    const int b  = blockIdx.z;
    const int h  = blockIdx.y;
    const int q0 = blockIdx.x * 64;
    const int tid  = threadIdx.x;
    const int lane = tid & 31;
    const int w    = tid >> 5;
    const int g    = lane >> 2;
    const int tg   = lane & 3;
    const size_t hoff = ((size_t)(b * NHEADS + h)) * SEQ * HDIM;

#pragma unroll
    for (int i = 0; i < 8; i++) {
        const int idx = tid + i * 128;
        const int row = idx >> 4;
        const int c4  = (idx & 15) << 2;
        float4 t = *(const float4*)(Q + hoff + (size_t)(q0 + row) * HDIM + c4);
        float4 o;
        o.x = f2tf32(t.x * 0.125f); o.y = f2tf32(t.y * 0.125f);
        o.z = f2tf32(t.z * 0.125f); o.w = f2tf32(t.w * 0.125f);
        *(float4*)(sQ + row * ASTR + c4) = o;
    }
    __syncthreads();

    unsigned aQ[8][4];
    {
        const float* qb = sQ + (w * 16 + g) * ASTR;
#pragma unroll
        for (int kk = 0; kk < 8; kk++) {
            aQ[kk][0] = __float_as_uint(qb[kk * 8 + tg]);
            aQ[kk][1] = __float_as_uint(qb[8 * ASTR + kk * 8 + tg]);
            aQ[kk][2] = __float_as_uint(qb[kk * 8 + tg + 4]);
            aQ[kk][3] = __float_as_uint(qb[8 * ASTR + kk * 8 + tg + 4]);
        }
    }

    float cO[8][4];
#pragma unroll
    for (int nt = 0; nt < 8; nt++)
#pragma unroll
        for (int r = 0; r < 4; r++) cO[nt][r] = 0.f;
    float mrow[2] = { -1e30f, -1e30f };
    float lrow[2] = { 0.f, 0.f };

    const int ntiles = CAUSAL ? (q0 / 64 + 1) : (SEQ / 64);

    for (int t = 0; t < ntiles; t++) {
        const int j0 = t * 64;
        __syncthreads();
#pragma unroll
        for (int i = 0; i < 8; i++) {
            const int idx = tid + i * 128;
            const int row = idx >> 4;
            const int c4  = (idx & 15) << 2;
            const size_t gaddr = hoff + (size_t)(j0 + row) * HDIM + c4;
            float4 kt = *(const float4*)(K + gaddr);
            float4 ko;
            ko.x = f2tf32(kt.x); ko.y = f2tf32(kt.y);
            ko.z = f2tf32(kt.z); ko.w = f2tf32(kt.w);
            *(float4*)(sK + row * ASTR + c4) = ko;
            float4 vt = *(const float4*)(V + gaddr);
            float4 vo;
            vo.x = f2tf32(vt.x); vo.y = f2tf32(vt.y);
            vo.z = f2tf32(vt.z); vo.w = f2tf32(vt.w);
            *(float4*)(sV + row * ASTR + c4) = vo;
        }
        __syncthreads();

        float cS[8][4];
#pragma unroll
        for (int nt = 0; nt < 8; nt++)
#pragma unroll
            for (int r = 0; r < 4; r++) cS[nt][r] = 0.f;

#pragma unroll
        for (int kk = 0; kk < 8; kk++)
#pragma unroll
            for (int nt = 0; nt < 8; nt++) {
                const float* kp = sK + (nt * 8 + g) * ASTR + kk * 8 + tg;
                unsigned b0 = __float_as_uint(kp[0]);
                unsigned b1 = __float_as_uint(kp[4]);
                MMA_TF32(cS[nt], aQ[kk], b0, b1);
            }

        if (CAUSAL && t == ntiles - 1) {
            const int rbase = q0 + w * 16 + g;
#pragma unroll
            for (int nt = 0; nt < 8; nt++) {
                const int c0 = j0 + nt * 8 + tg * 2;
                if (c0     > rbase)     cS[nt][0] = -1e30f;
                if (c0 + 1 > rbase)     cS[nt][1] = -1e30f;
                if (c0     > rbase + 8) cS[nt][2] = -1e30f;
                if (c0 + 1 > rbase + 8) cS[nt][3] = -1e30f;
            }
        }

        float* pb = sP + (w * 16) * ASTR;
#pragma unroll
        for (int rh = 0; rh < 2; rh++) {
            float mx = -1e30f;
#pragma unroll
            for (int nt = 0; nt < 8; nt++)
                mx = fmaxf(mx, fmaxf(cS[nt][2 * rh], cS[nt][2 * rh + 1]));
            mx = fmaxf(mx, __shfl_xor_sync(0xffffffffu, mx, 1));
            mx = fmaxf(mx, __shfl_xor_sync(0xffffffffu, mx, 2));
            const float mnew = fmaxf(mrow[rh], mx);
            const float corr = __expf(mrow[rh] - mnew);
            float sum = 0.f;
#pragma unroll
            for (int nt = 0; nt < 8; nt++) {
                float p0 = __expf(cS[nt][2 * rh]     - mnew);
                float p1 = __expf(cS[nt][2 * rh + 1] - mnew);
                cS[nt][2 * rh]     = p0;
                cS[nt][2 * rh + 1] = p1;
                sum += p0 + p1;
            }
            sum += __shfl_xor_sync(0xffffffffu, sum, 1);
            sum += __shfl_xor_sync(0xffffffffu, sum, 2);
            lrow[rh] = lrow[rh] * corr + sum;
            mrow[rh] = mnew;
#pragma unroll
            for (int nt = 0; nt < 8; nt++) {
                cO[nt][2 * rh]     *= corr;
                cO[nt][2 * rh + 1] *= corr;
            }
            float* prow = pb + (g + 8 * rh) * ASTR;
#pragma unroll
            for (int nt = 0; nt < 8; nt++) {
                float2 pv;
                pv.x = f2tf32(cS[nt][2 * rh]);
                pv.y = f2tf32(cS[nt][2 * rh + 1]);
                *(float2*)(prow + nt * 8 + tg * 2) = pv;
            }
        }
        __syncwarp();

#pragma unroll
        for (int kk = 0; kk < 8; kk++) {
            unsigned aP[4];
            aP[0] = __float_as_uint(pb[g * ASTR + kk * 8 + tg]);
            aP[1] = __float_as_uint(pb[(g + 8) * ASTR + kk * 8 + tg]);
            aP[2] = __float_as_uint(pb[g * ASTR + kk * 8 + tg + 4]);
            aP[3] = __float_as_uint(pb[(g + 8) * ASTR + kk * 8 + tg + 4]);
#pragma unroll
            for (int nt = 0; nt < 8; nt++) {
                const float* vp0 = sV + (kk * 8 + tg) * ASTR + nt * 8 + g;
                const float* vp1 = sV + (kk * 8 + tg + 4) * ASTR + nt * 8 + g;
                unsigned b0 = __float_as_uint(vp0[0]);
                unsigned b1 = __float_as_uint(vp1[0]);
                MMA_TF32(cO[nt], aP, b0, b1);
            }
        }
    }

    const float inv0 = 1.f / lrow[0];
    const float inv1 = 1.f / lrow[1];
    const int r0 = q0 + w * 16 + g;
    float* o0p = O + (size_t)(b * SEQ + r0) * DMODEL + h * HDIM;
    float* o1p = O + (size_t)(b * SEQ + r0 + 8) * DMODEL + h * HDIM;
#pragma unroll
    for (int nt = 0; nt < 8; nt++) {
        const int c = nt * 8 + tg * 2;
        float2 v0, v1;
        v0.x = cO[nt][0] * inv0; v0.y = cO[nt][1] * inv0;
        v1.x = cO[nt][2] * inv1; v1.y = cO[nt][3] * inv1;
        *(float2*)(o0p + c) = v0;
        *(float2*)(o1p + c) = v1;
    }
}

// ----------------------------------------------------------------------------
// LayerNorm (unchanged)
// ----------------------------------------------------------------------------
__global__ __launch_bounds__(256) void ln_kernel(
    const float* __restrict__ X, const float* __restrict__ g,
    const float* __restrict__ bb, float* __restrict__ Y)
{
    __shared__ float red[16];
    const int row = blockIdx.x;
    const int tid = threadIdx.x;
    const float4 xv = *(const float4*)(X + (size_t)row * DMODEL + tid * 4);

    float s  = xv.x + xv.y + xv.z + xv.w;
    float sq = xv.x*xv.x + xv.y*xv.y + xv.z*xv.z + xv.w*xv.w;
#pragma unroll
    for (int off = 16; off > 0; off >>= 1) {
        s  += __shfl_xor_sync(0xffffffffu, s,  off);
        sq += __shfl_xor_sync(0xffffffffu, sq, off);
    }
    const int warp = tid >> 5, lane = tid & 31;
    if (lane == 0) { red[warp] = s; red[warp + 8] = sq; }
    __syncthreads();
    if (warp == 0) {
        float a = (lane < 8) ? red[lane] : 0.f;
        float c = (lane < 8) ? red[lane + 8] : 0.f;
#pragma unroll
        for (int off = 4; off > 0; off >>= 1) {
            a += __shfl_xor_sync(0xffffffffu, a, off);
            c += __shfl_xor_sync(0xffffffffu, c, off);
        }
        if (lane == 0) { red[0] = a; red[1] = c; }
    }
    __syncthreads();
    const float mu  = red[0] * (1.f / DMODEL);
    const float var = red[1] * (1.f / DMODEL) - mu * mu;
    const float rstd = rsqrtf(var + LN_EPS);

    const float4 gv = *(const float4*)(g  + tid * 4);
    const float4 bv = *(const float4*)(bb + tid * 4);
    float4 yv;
    yv.x = (xv.x - mu) * rstd * gv.x + bv.x;
    yv.y = (xv.y - mu) * rstd * gv.y + bv.y;
    yv.z = (xv.z - mu) * rstd * gv.z + bv.z;
    yv.w = (xv.w - mu) * rstd * gv.w + bv.w;
    *(float4*)(Y + (size_t)row * DMODEL + tid * 4) = yv;
}

// ----------------------------------------------------------------------------
// Launch
// ----------------------------------------------------------------------------
extern "C" void kernel_launch(void* const* d_in, const int* in_sizes, int n_in,
                              void* d_out, int out_size)
{
    const float* x    = (const float*)d_in[0];
    const float* enc  = (const float*)d_in[1];
    const float* s_wq = (const float*)d_in[2];  const float* s_bq = (const float*)d_in[3];
    const float* s_wk = (const float*)d_in[4];  const float* s_bk = (const float*)d_in[5];
    const float* s_wv = (const float*)d_in[6];  const float* s_bv = (const float*)d_in[7];
    const float* s_wo = (const float*)d_in[8];  const float* s_bo = (const float*)d_in[9];
    const float* c_wq = (const float*)d_in[10]; const float* c_bq = (const float*)d_in[11];
    const float* c_wk = (const float*)d_in[12]; const float* c_bk = (const float*)d_in[13];
    const float* c_wv = (const float*)d_in[14]; const float* c_bv = (const float*)d_in[15];
    const float* c_wo = (const float*)d_in[16]; const float* c_bo = (const float*)d_in[17];
    const float* f_w1 = (const float*)d_in[18]; const float* f_b1 = (const float*)d_in[19];
    const float* f_w2 = (const float*)d_in[20]; const float* f_b2 = (const float*)d_in[21];
    const float* ln1g = (const float*)d_in[22]; const float* ln1b = (const float*)d_in[23];
    const float* ln2g = (const float*)d_in[24]; const float* ln2b = (const float*)d_in[25];
    const float* ln3g = (const float*)d_in[26]; const float* ln3b = (const float*)d_in[27];
    float* out = (float*)d_out;

    float *q, *k, *v, *attn, *tmp, *y1, *y2, *ffn;
    cudaGetSymbolAddress((void**)&q,    g_q);
    cudaGetSymbolAddress((void**)&k,    g_k);
    cudaGetSymbolAddress((void**)&v,    g_v);
    cudaGetSymbolAddress((void**)&attn, g_attn);
    cudaGetSymbolAddress((void**)&tmp,  g_tmp);
    cudaGetSymbolAddress((void**)&y1,   g_y1);
    cudaGetSymbolAddress((void**)&y2,   g_y2);
    cudaGetSymbolAddress((void**)&ffn,  g_ffn);

    cudaFuncSetAttribute(attn_tc<true>,
        cudaFuncAttributeMaxDynamicSharedMemorySize, ATT_SMEM);
    cudaFuncSetAttribute(attn_tc<false>,
        cudaFuncAttributeMaxDynamicSharedMemorySize, ATT_SMEM);

    const dim3 blk(256);
    const dim3 ablk(128);
    const dim3 gatt(SEQ / 64, NHEADS, BATCH);
    const dim3 gln(TOK);

    GemmArgs ga;

    // ---- self attention: fused QKV projection (z=3) ----
    ga = GemmArgs{};
    ga.A[0] = x;    ga.A[1] = x;    ga.A[2] = x;
    ga.W[0] = s_wq; ga.W[1] = s_wk; ga.W[2] = s_wv;
    ga.bias[0] = s_bq; ga.bias[1] = s_bk; ga.bias[2] = s_bv;
    ga.R[0] = x; ga.R[1] = x; ga.R[2] = x;
    ga.C[0] = q; ga.C[1] = k; ga.C[2] = v;
    ga.N = DMODEL; ga.K = DMODEL;
    gemm_bf16<false,false><<<dim3(DMODEL/128, TOK/128, 3), blk>>>(ga);

    attn_tc<true><<<gatt, ablk, ATT_SMEM>>>(q, k, v, attn);

    ga.A[0] = attn; ga.W[0] = s_wo; ga.bias[0] = s_bo; ga.R[0] = x; ga.C[0] = tmp;
    gemm_bf16<false,true><<<dim3(DMODEL/128, TOK/128, 1), blk>>>(ga);
    ln_kernel<<<gln, blk>>>(tmp, ln1g, ln1b, y1);

    // ---- cross attention: fused Q(y1) + K,V(enc) projection (z=3) ----
    ga.A[0] = y1;   ga.A[1] = enc;  ga.A[2] = enc;
    ga.W[0] = c_wq; ga.W[1] = c_wk; ga.W[2] = c_wv;
    ga.bias[0] = c_bq; ga.bias[1] = c_bk; ga.bias[2] = c_bv;
    ga.R[0] = x; ga.R[1] = x; ga.R[2] = x;
    ga.C[0] = q; ga.C[1] = k; ga.C[2] = v;
    gemm_bf16<false,false><<<dim3(DMODEL/128, TOK/128, 3), blk>>>(ga);

    attn_tc<false><<<gatt, ablk, ATT_SMEM>>>(q, k, v, attn);

    ga.A[0] = attn; ga.W[0] = c_wo; ga.bias[0] = c_bo; ga.R[0] = y1; ga.C[0] = tmp;
    gemm_bf16<false,true><<<dim3(DMODEL/128, TOK/128, 1), blk>>>(ga);
    ln_kernel<<<gln, blk>>>(tmp, ln2g, ln2b, y2);

    // ---- FFN ----
    ga.A[0] = y2; ga.W[0] = f_w1; ga.bias[0] = f_b1; ga.R[0] = x; ga.C[0] = ffn;
    ga.N = DFF; ga.K = DMODEL;
    gemm_bf16<true,false><<<dim3(DFF/128, TOK/128, 1), blk>>>(ga);

    ga.A[0] = ffn; ga.W[0] = f_w2; ga.bias[0] = f_b2; ga.R[0] = y2; ga.C[0] = tmp;
    ga.N = DMODEL; ga.K = DFF;
    gemm_bf16<false,true><<<dim3(DMODEL/128, TOK/128, 1), blk>>>(ga);
    ln_kernel<<<gln, blk>>>(tmp, ln3g, ln3b, out);
}

// round 12
// speedup vs baseline: 1.7423x; 1.3282x over previous
#include <cuda_runtime.h>
#include <cuda_bf16.h>
#include <math.h>
#include <stdint.h>

// ----------------------------------------------------------------------------
// Problem constants
// ----------------------------------------------------------------------------
#define BATCH   2
#define SEQ     2048
#define TOK     (BATCH * SEQ)        // 4096 rows
#define DMODEL  1024
#define DFF     4096
#define NHEADS  16
#define HDIM    64
#define LN_EPS  1e-5f

// ----------------------------------------------------------------------------
// Scratch buffers
// ----------------------------------------------------------------------------
__device__ float g_q   [TOK * DMODEL];
__device__ float g_k   [TOK * DMODEL];
__device__ float g_v   [TOK * DMODEL];
__device__ float g_attn[TOK * DMODEL];
__device__ float g_tmp [TOK * DMODEL];
__device__ float g_y1  [TOK * DMODEL];
__device__ float g_y2  [TOK * DMODEL];
__device__ float g_ffn [TOK * DFF];

// pack two fp32 -> bf16x2 / f16x2 (first asm src -> HIGH half)
__device__ __forceinline__ uint32_t packbf(float lo, float hi) {
    uint32_t d;
    asm("cvt.rn.bf16x2.f32 %0, %1, %2;" : "=r"(d) : "f"(hi), "f"(lo));
    return d;
}
__device__ __forceinline__ uint32_t packh(float lo, float hi) {
    uint32_t d;
    asm("cvt.rn.f16x2.f32 %0, %1, %2;" : "=r"(d) : "f"(hi), "f"(lo));
    return d;
}
__device__ __forceinline__ uint32_t ex2h2(uint32_t x) {
    uint32_t r;
    asm("ex2.approx.f16x2 %0, %1;" : "=r"(r) : "r"(x));
    return r;
}
__device__ __forceinline__ uint32_t smem_u32(const void* p) {
    return (uint32_t)__cvta_generic_to_shared(p);
}

#define MMA_BF16(acc, a, b0v, b1v)                                         \
    asm volatile(                                                          \
        "mma.sync.aligned.m16n8k16.row.col.f32.bf16.bf16.f32 "             \
        "{%0,%1,%2,%3}, {%4,%5,%6,%7}, {%8,%9}, {%0,%1,%2,%3};"            \
        : "+f"((acc)[0]), "+f"((acc)[1]), "+f"((acc)[2]), "+f"((acc)[3])   \
        : "r"((a)[0]), "r"((a)[1]), "r"((a)[2]), "r"((a)[3]),              \
          "r"(b0v), "r"(b1v))

#define MMA_F16(acc, a, b0v, b1v)                                          \
    asm volatile(                                                          \
        "mma.sync.aligned.m16n8k16.row.col.f32.f16.f16.f32 "               \
        "{%0,%1,%2,%3}, {%4,%5,%6,%7}, {%8,%9}, {%0,%1,%2,%3};"            \
        : "+f"((acc)[0]), "+f"((acc)[1]), "+f"((acc)[2]), "+f"((acc)[3])   \
        : "r"((a)[0]), "r"((a)[1]), "r"((a)[2]), "r"((a)[3]),              \
          "r"(b0v), "r"(b1v))

#define LDSM_X4_TRANS(r0, r1, r2, r3, addr)                                \
    asm volatile(                                                          \
        "ldmatrix.sync.aligned.m8n8.x4.trans.shared.b16 "                  \
        "{%0,%1,%2,%3}, [%4];"                                             \
        : "=r"(r0), "=r"(r1), "=r"(r2), "=r"(r3) : "r"(addr))

// ----------------------------------------------------------------------------
// bf16 tensor-core GEMM (R8-validated, unchanged).
// ----------------------------------------------------------------------------
struct GemmArgs {
    const float* A[3];
    const float* W[3];
    const float* bias[3];
    const float* R[3];
    float*       C[3];
    int N, K;
};

#define A_WSTR 12
#define B_WSTR 136
#define A_WRDS (128 * A_WSTR)
#define B_WRDS (8 * B_WSTR)

template<bool RELU, bool RES>
__global__ __launch_bounds__(256, 2) void gemm_bf16(GemmArgs args)
{
    __shared__ uint32_t As[2][A_WRDS];
    __shared__ uint32_t Bs[2][B_WRDS];

    const int zi = blockIdx.z;
    const float* __restrict__ A    = args.A[zi];
    const float* __restrict__ W    = args.W[zi];
    const float* __restrict__ bias = args.bias[zi];
    const float* __restrict__ Rp   = args.R[zi];
    float*       __restrict__ C    = args.C[zi];
    const int N = args.N, K = args.K;

    const int tid  = threadIdx.x;
    const int lane = tid & 31;
    const int warp = tid >> 5;
    const int g    = lane >> 2;
    const int tg   = lane & 3;
    const int wm   = (warp >> 2) * 64;
    const int wn   = (warp & 3) * 32;
    const int bm   = blockIdx.y * 128;
    const int bn   = blockIdx.x * 128;

    const int a_row = tid >> 2;
    const int a_c4  = (tid & 3) * 4;
    const int b_p   = tid >> 5;
    const int b_c4  = (tid & 31) * 4;

    const float* Ag0 = A + (size_t)(bm + a_row)      * K + a_c4;
    const float* Ag1 = A + (size_t)(bm + a_row + 64) * K + a_c4;
    const float* Wg0 = W + (size_t)(2 * b_p)     * N + bn + b_c4;
    const float* Wg1 = W + (size_t)(2 * b_p + 1) * N + bn + b_c4;

    float acc[4][4][4];
#pragma unroll
    for (int i = 0; i < 4; i++)
#pragma unroll
        for (int j = 0; j < 4; j++)
#pragma unroll
            for (int r = 0; r < 4; r++) acc[i][j][r] = 0.f;

    float4 ra0, ra1, rb0, rb1;

#define LOADG(t) do {                                                \
        const size_t ka = (size_t)(t) * 16;                          \
        const size_t kb = (size_t)(t) * 16 * (size_t)N;              \
        ra0 = *(const float4*)(Ag0 + ka);                            \
        ra1 = *(const float4*)(Ag1 + ka);                            \
        rb0 = *(const float4*)(Wg0 + kb);                            \
        rb1 = *(const float4*)(Wg1 + kb);                            \
    } while (0)

#define STORES(buf) do {                                             \
        uint32_t* as_ = As[buf];                                     \
        uint32_t* bs_ = Bs[buf];                                     \
        uint2 aw0, aw1;                                              \
        aw0.x = packbf(ra0.x, ra0.y); aw0.y = packbf(ra0.z, ra0.w);  \
        aw1.x = packbf(ra1.x, ra1.y); aw1.y = packbf(ra1.z, ra1.w);  \
        *(uint2*)(as_ + a_row * A_WSTR + (a_c4 >> 1)) = aw0;         \
        *(uint2*)(as_ + (a_row + 64) * A_WSTR + (a_c4 >> 1)) = aw1;  \
        uint4 bw;                                                    \
        bw.x = packbf(rb0.x, rb1.x); bw.y = packbf(rb0.y, rb1.y);    \
        bw.z = packbf(rb0.z, rb1.z); bw.w = packbf(rb0.w, rb1.w);    \
        *(uint4*)(bs_ + b_p * B_WSTR + b_c4) = bw;                   \
    } while (0)

    const int NT = K >> 4;

    LOADG(0);
    STORES(0);
    __syncthreads();

    for (int t = 0; t < NT; t++) {
        const int cur = t & 1;
        if (t + 1 < NT) LOADG(t + 1);

        const uint32_t* as_ = As[cur];
        const uint32_t* bs_ = Bs[cur];

        unsigned af[4][4], bf2[4][2];
#pragma unroll
        for (int mt = 0; mt < 4; mt++) {
            const uint32_t* ap = as_ + (wm + mt * 16 + g) * A_WSTR + tg;
            af[mt][0] = ap[0];
            af[mt][1] = ap[8 * A_WSTR];
            af[mt][2] = ap[4];
            af[mt][3] = ap[8 * A_WSTR + 4];
        }
#pragma unroll
        for (int nt = 0; nt < 4; nt++) {
            const int col = wn + nt * 8 + g;
            bf2[nt][0] = bs_[tg * B_WSTR + col];
            bf2[nt][1] = bs_[(tg + 4) * B_WSTR + col];
        }
#pragma unroll
        for (int mt = 0; mt < 4; mt++)
#pragma unroll
            for (int nt = 0; nt < 4; nt++)
                MMA_BF16(acc[mt][nt], af[mt], bf2[nt][0], bf2[nt][1]);

        if (t + 1 < NT) STORES((t + 1) & 1);
        __syncthreads();
    }

#pragma unroll
    for (int mt = 0; mt < 4; mt++) {
        const int row0 = bm + wm + mt * 16 + g;
#pragma unroll
        for (int nt = 0; nt < 4; nt++) {
            const int col = bn + wn + nt * 8 + tg * 2;
            const float bv0 = bias[col], bv1 = bias[col + 1];
            float2 v0, v1;
            v0.x = acc[mt][nt][0] + bv0; v0.y = acc[mt][nt][1] + bv1;
            v1.x = acc[mt][nt][2] + bv0; v1.y = acc[mt][nt][3] + bv1;
            if (RES) {
                float2 r0 = *(const float2*)(Rp + (size_t)row0 * N + col);
                float2 r1 = *(const float2*)(Rp + (size_t)(row0 + 8) * N + col);
                v0.x += r0.x; v0.y += r0.y;
                v1.x += r1.x; v1.y += r1.y;
            }
            if (RELU) {
                v0.x = fmaxf(v0.x, 0.f); v0.y = fmaxf(v0.y, 0.f);
                v1.x = fmaxf(v1.x, 0.f); v1.y = fmaxf(v1.y, 0.f);
            }
            *(float2*)(C + (size_t)row0 * N + col)       = v0;
            *(float2*)(C + (size_t)(row0 + 8) * N + col) = v1;
        }
    }
#undef LOADG
#undef STORES
}

// ----------------------------------------------------------------------------
// fp16 flash attention, MUFU-optimized (R11 design, Q-row offset FIXED).
// ----------------------------------------------------------------------------
#define HSTR 72            // halves per smem row (64 + 8 pad)
#define QSCALE (0.125f * 1.44269504f)

template<bool CAUSAL>
__global__ __launch_bounds__(128) void attn_fp16(
    const float* __restrict__ Q, const float* __restrict__ K,
    const float* __restrict__ V, float* __restrict__ O)
{
    __shared__ __align__(16) uint16_t sQ[64 * HSTR];
    __shared__ __align__(16) uint16_t sK[64 * HSTR];
    __shared__ __align__(16) uint16_t sV[64 * HSTR];
    uint32_t* sQw = (uint32_t*)sQ;     // word stride 36
    uint32_t* sKw = (uint32_t*)sK;

    const int b  = blockIdx.z;
    const int h  = blockIdx.y;
    const int q0 = blockIdx.x * 64;
    const int tid  = threadIdx.x;
    const int lane = tid & 31;
    const int w    = tid >> 5;
    const int g    = lane >> 2;
    const int tg   = lane & 3;
    const size_t hoff = ((size_t)(b * NHEADS + h)) * SEQ * HDIM;
    const uint32_t sVbase = smem_u32(sV);

    // ---- stage Q (scale folded into fp16) ----
#pragma unroll
    for (int i = 0; i < 8; i++) {
        const int idx = tid + i * 128;
        const int row = idx >> 4;
        const int c4  = (idx & 15) << 2;
        float4 t = *(const float4*)(Q + hoff + (size_t)(q0 + row) * HDIM + c4);
        sQw[row * 36 + (c4 >> 1)]     = packh(t.x * QSCALE, t.y * QSCALE);
        sQw[row * 36 + (c4 >> 1) + 1] = packh(t.z * QSCALE, t.w * QSCALE);
    }
    __syncthreads();

    // ---- Q fragments (register resident); rows = w*16 + {g, g+8} ----
    uint32_t aQ[4][4];
#pragma unroll
    for (int kk = 0; kk < 4; kk++) {
        const uint32_t* qb = sQw + (w * 16 + g) * 36 + kk * 8 + tg;
        aQ[kk][0] = qb[0];
        aQ[kk][1] = qb[8 * 36];
        aQ[kk][2] = qb[4];
        aQ[kk][3] = qb[8 * 36 + 4];
    }

    float cO[8][4];
#pragma unroll
    for (int nt = 0; nt < 8; nt++)
#pragma unroll
        for (int r = 0; r < 4; r++) cO[nt][r] = 0.f;
    float lrow[2] = { 0.f, 0.f };

    const int ntiles = CAUSAL ? (q0 / 64 + 1) : (SEQ / 64);

    for (int t = 0; t < ntiles; t++) {
        const int j0 = t * 64;
        __syncthreads();
        // ---- stage K, V (fp16) ----
#pragma unroll
        for (int i = 0; i < 8; i++) {
            const int idx = tid + i * 128;
            const int row = idx >> 4;
            const int c4  = (idx & 15) << 2;
            const size_t gaddr = hoff + (size_t)(j0 + row) * HDIM + c4;
            float4 kt = *(const float4*)(K + gaddr);
            sKw[row * 36 + (c4 >> 1)]     = packh(kt.x, kt.y);
            sKw[row * 36 + (c4 >> 1) + 1] = packh(kt.z, kt.w);
            float4 vt = *(const float4*)(V + gaddr);
            ((uint32_t*)sV)[row * 36 + (c4 >> 1)]     = packh(vt.x, vt.y);
            ((uint32_t*)sV)[row * 36 + (c4 >> 1) + 1] = packh(vt.z, vt.w);
        }
        __syncthreads();

        // ---- S = Q @ K^T (log2 domain; scale pre-folded) ----
        float cS[8][4];
#pragma unroll
        for (int nt = 0; nt < 8; nt++)
#pragma unroll
            for (int r = 0; r < 4; r++) cS[nt][r] = 0.f;

#pragma unroll
        for (int kk = 0; kk < 4; kk++)
#pragma unroll
            for (int nt = 0; nt < 8; nt++) {
                const uint32_t* kp = sKw + (nt * 8 + g) * 36 + kk * 8 + tg;
                MMA_F16(cS[nt], aQ[kk], kp[0], kp[4]);
            }

        // ---- causal mask (diagonal tile only) ----
        if (CAUSAL && t == ntiles - 1) {
            const int rbase = q0 + w * 16 + g;
#pragma unroll
            for (int nt = 0; nt < 8; nt++) {
                const int c0 = j0 + nt * 8 + tg * 2;
                if (c0     > rbase)     cS[nt][0] = -1e30f;
                if (c0 + 1 > rbase)     cS[nt][1] = -1e30f;
                if (c0     > rbase + 8) cS[nt][2] = -1e30f;
                if (c0 + 1 > rbase + 8) cS[nt][3] = -1e30f;
            }
        }

        // ---- p = 2^S, packed f16x2 (these ARE the PV A-frag words) ----
        uint32_t plo[8], phi[8];
#pragma unroll
        for (int nt = 0; nt < 8; nt++) {
            plo[nt] = ex2h2(packh(cS[nt][0], cS[nt][1]));
            phi[nt] = ex2h2(packh(cS[nt][2], cS[nt][3]));
        }

        uint32_t aP[4][4];
#pragma unroll
        for (int kk = 0; kk < 4; kk++) {
            aP[kk][0] = plo[2 * kk];
            aP[kk][1] = phi[2 * kk];
            aP[kk][2] = plo[2 * kk + 1];
            aP[kk][3] = phi[2 * kk + 1];
        }

        // ---- row sums via mma with B = ones (fp32 accumulate) ----
        {
            float cSum[4] = { 0.f, 0.f, 0.f, 0.f };
#pragma unroll
            for (int kk = 0; kk < 4; kk++)
                MMA_F16(cSum, aP[kk], 0x3C003C00u, 0x3C003C00u);
            lrow[0] += cSum[0];
            lrow[1] += cSum[2];
        }

        // ---- O += P @ V : V B-frags via ldmatrix.x4.trans ----
#pragma unroll
        for (int kk = 0; kk < 4; kk++)
#pragma unroll
            for (int np = 0; np < 4; np++) {
                const int mat = lane >> 3;
                const int r   = lane & 7;
                const int key = kk * 16 + (mat & 1) * 8 + r;
                const int dcl = np * 16 + (mat >> 1) * 8;
                const uint32_t addr = sVbase + (uint32_t)(key * HSTR + dcl) * 2;
                uint32_t v0, v1, v2, v3;
                LDSM_X4_TRANS(v0, v1, v2, v3, addr);
                MMA_F16(cO[2 * np],     aP[kk], v0, v1);
                MMA_F16(cO[2 * np + 1], aP[kk], v2, v3);
            }
    }

    // ---- epilogue: normalize and store (folds head transpose) ----
    const float inv0 = 1.f / lrow[0];
    const float inv1 = 1.f / lrow[1];
    const int r0 = q0 + w * 16 + g;
    float* o0p = O + (size_t)(b * SEQ + r0) * DMODEL + h * HDIM;
    float* o1p = O + (size_t)(b * SEQ + r0 + 8) * DMODEL + h * HDIM;
#pragma unroll
    for (int nt = 0; nt < 8; nt++) {
        const int c = nt * 8 + tg * 2;
        float2 v0, v1;
        v0.x = cO[nt][0] * inv0; v0.y = cO[nt][1] * inv0;
        v1.x = cO[nt][2] * inv1; v1.y = cO[nt][3] * inv1;
        *(float2*)(o0p + c) = v0;
        *(float2*)(o1p + c) = v1;
    }
}

// ----------------------------------------------------------------------------
// LayerNorm (unchanged)
// ----------------------------------------------------------------------------
__global__ __launch_bounds__(256) void ln_kernel(
    const float* __restrict__ X, const float* __restrict__ g,
    const float* __restrict__ bb, float* __restrict__ Y)
{
    __shared__ float red[16];
    const int row = blockIdx.x;
    const int tid = threadIdx.x;
    const float4 xv = *(const float4*)(X + (size_t)row * DMODEL + tid * 4);

    float s  = xv.x + xv.y + xv.z + xv.w;
    float sq = xv.x*xv.x + xv.y*xv.y + xv.z*xv.z + xv.w*xv.w;
#pragma unroll
    for (int off = 16; off > 0; off >>= 1) {
        s  += __shfl_xor_sync(0xffffffffu, s,  off);
        sq += __shfl_xor_sync(0xffffffffu, sq, off);
    }
    const int warp = tid >> 5, lane = tid & 31;
    if (lane == 0) { red[warp] = s; red[warp + 8] = sq; }
    __syncthreads();
    if (warp == 0) {
        float a = (lane < 8) ? red[lane] : 0.f;
        float c = (lane < 8) ? red[lane + 8] : 0.f;
#pragma unroll
        for (int off = 4; off > 0; off >>= 1) {
            a += __shfl_xor_sync(0xffffffffu, a, off);
            c += __shfl_xor_sync(0xffffffffu, c, off);
        }
        if (lane == 0) { red[0] = a; red[1] = c; }
    }
    __syncthreads();
    const float mu  = red[0] * (1.f / DMODEL);
    const float var = red[1] * (1.f / DMODEL) - mu * mu;
    const float rstd = rsqrtf(var + LN_EPS);

    const float4 gv = *(const float4*)(g  + tid * 4);
    const float4 bv = *(const float4*)(bb + tid * 4);
    float4 yv;
    yv.x = (xv.x - mu) * rstd * gv.x + bv.x;
    yv.y = (xv.y - mu) * rstd * gv.y + bv.y;
    yv.z = (xv.z - mu) * rstd * gv.z + bv.z;
    yv.w = (xv.w - mu) * rstd * gv.w + bv.w;
    *(float4*)(Y + (size_t)row * DMODEL + tid * 4) = yv;
}

// ----------------------------------------------------------------------------
// Launch
// ----------------------------------------------------------------------------
extern "C" void kernel_launch(void* const* d_in, const int* in_sizes, int n_in,
                              void* d_out, int out_size)
{
    const float* x    = (const float*)d_in[0];
    const float* enc  = (const float*)d_in[1];
    const float* s_wq = (const float*)d_in[2];  const float* s_bq = (const float*)d_in[3];
    const float* s_wk = (const float*)d_in[4];  const float* s_bk = (const float*)d_in[5];
    const float* s_wv = (const float*)d_in[6];  const float* s_bv = (const float*)d_in[7];
    const float* s_wo = (const float*)d_in[8];  const float* s_bo = (const float*)d_in[9];
    const float* c_wq = (const float*)d_in[10]; const float* c_bq = (const float*)d_in[11];
    const float* c_wk = (const float*)d_in[12]; const float* c_bk = (const float*)d_in[13];
    const float* c_wv = (const float*)d_in[14]; const float* c_bv = (const float*)d_in[15];
    const float* c_wo = (const float*)d_in[16]; const float* c_bo = (const float*)d_in[17];
    const float* f_w1 = (const float*)d_in[18]; const float* f_b1 = (const float*)d_in[19];
    const float* f_w2 = (const float*)d_in[20]; const float* f_b2 = (const float*)d_in[21];
    const float* ln1g = (const float*)d_in[22]; const float* ln1b = (const float*)d_in[23];
    const float* ln2g = (const float*)d_in[24]; const float* ln2b = (const float*)d_in[25];
    const float* ln3g = (const float*)d_in[26]; const float* ln3b = (const float*)d_in[27];
    float* out = (float*)d_out;

    float *q, *k, *v, *attn, *tmp, *y1, *y2, *ffn;
    cudaGetSymbolAddress((void**)&q,    g_q);
    cudaGetSymbolAddress((void**)&k,    g_k);
    cudaGetSymbolAddress((void**)&v,    g_v);
    cudaGetSymbolAddress((void**)&attn, g_attn);
    cudaGetSymbolAddress((void**)&tmp,  g_tmp);
    cudaGetSymbolAddress((void**)&y1,   g_y1);
    cudaGetSymbolAddress((void**)&y2,   g_y2);
    cudaGetSymbolAddress((void**)&ffn,  g_ffn);

    const dim3 blk(256);
    const dim3 ablk(128);
    const dim3 gatt(SEQ / 64, NHEADS, BATCH);
    const dim3 gln(TOK);

    GemmArgs ga;

    // ---- self attention: fused QKV projection (z=3) ----
    ga = GemmArgs{};
    ga.A[0] = x;    ga.A[1] = x;    ga.A[2] = x;
    ga.W[0] = s_wq; ga.W[1] = s_wk; ga.W[2] = s_wv;
    ga.bias[0] = s_bq; ga.bias[1] = s_bk; ga.bias[2] = s_bv;
    ga.R[0] = x; ga.R[1] = x; ga.R[2] = x;
    ga.C[0] = q; ga.C[1] = k; ga.C[2] = v;
    ga.N = DMODEL; ga.K = DMODEL;
    gemm_bf16<false,false><<<dim3(DMODEL/128, TOK/128, 3), blk>>>(ga);

    attn_fp16<true><<<gatt, ablk>>>(q, k, v, attn);

    ga.A[0] = attn; ga.W[0] = s_wo; ga.bias[0] = s_bo; ga.R[0] = x; ga.C[0] = tmp;
    gemm_bf16<false,true><<<dim3(DMODEL/128, TOK/128, 1), blk>>>(ga);
    ln_kernel<<<gln, blk>>>(tmp, ln1g, ln1b, y1);

    // ---- cross attention: fused Q(y1) + K,V(enc) projection (z=3) ----
    ga.A[0] = y1;   ga.A[1] = enc;  ga.A[2] = enc;
    ga.W[0] = c_wq; ga.W[1] = c_wk; ga.W[2] = c_wv;
    ga.bias[0] = c_bq; ga.bias[1] = c_bk; ga.bias[2] = c_bv;
    ga.R[0] = x; ga.R[1] = x; ga.R[2] = x;
    ga.C[0] = q; ga.C[1] = k; ga.C[2] = v;
    gemm_bf16<false,false><<<dim3(DMODEL/128, TOK/128, 3), blk>>>(ga);

    attn_fp16<false><<<gatt, ablk>>>(q, k, v, attn);

    ga.A[0] = attn; ga.W[0] = c_wo; ga.bias[0] = c_bo; ga.R[0] = y1; ga.C[0] = tmp;
    gemm_bf16<false,true><<<dim3(DMODEL/128, TOK/128, 1), blk>>>(ga);
    ln_kernel<<<gln, blk>>>(tmp, ln2g, ln2b, y2);

    // ---- FFN ----
    ga.A[0] = y2; ga.W[0] = f_w1; ga.bias[0] = f_b1; ga.R[0] = x; ga.C[0] = ffn;
    ga.N = DFF; ga.K = DMODEL;
    gemm_bf16<true,false><<<dim3(DFF/128, TOK/128, 1), blk>>>(ga);

    ga.A[0] = ffn; ga.W[0] = f_w2; ga.bias[0] = f_b2; ga.R[0] = y2; ga.C[0] = tmp;
    ga.N = DMODEL; ga.K = DFF;
    gemm_bf16<false,true><<<dim3(DMODEL/128, TOK/128, 1), blk>>>(ga);
    ln_kernel<<<gln, blk>>>(tmp, ln3g, ln3b, out);
}

// round 13
// speedup vs baseline: 1.8138x; 1.0410x over previous
#include <cuda_runtime.h>
#include <cuda_bf16.h>
#include <math.h>
#include <stdint.h>

// ----------------------------------------------------------------------------
// Problem constants
// ----------------------------------------------------------------------------
#define BATCH   2
#define SEQ     2048
#define TOK     (BATCH * SEQ)        // 4096 rows
#define DMODEL  1024
#define DFF     4096
#define NHEADS  16
#define HDIM    64
#define LN_EPS  1e-5f
#define QSCALE  (0.125f * 1.44269504f)

// ----------------------------------------------------------------------------
// Scratch buffers
// ----------------------------------------------------------------------------
__device__ uint16_t h_q [TOK * DMODEL];   // fp16 Q (pre-scaled by QSCALE)
__device__ uint16_t h_k [TOK * DMODEL];   // fp16 K
__device__ uint16_t h_v [TOK * DMODEL];   // fp16 V
__device__ float g_attn[TOK * DMODEL];
__device__ float g_tmp [TOK * DMODEL];
__device__ float g_y1  [TOK * DMODEL];
__device__ float g_y2  [TOK * DMODEL];
__device__ float g_ffn [TOK * DFF];

// pack two fp32 -> bf16x2 / f16x2 (first asm src -> HIGH half)
__device__ __forceinline__ uint32_t packbf(float lo, float hi) {
    uint32_t d;
    asm("cvt.rn.bf16x2.f32 %0, %1, %2;" : "=r"(d) : "f"(hi), "f"(lo));
    return d;
}
__device__ __forceinline__ uint32_t packh(float lo, float hi) {
    uint32_t d;
    asm("cvt.rn.f16x2.f32 %0, %1, %2;" : "=r"(d) : "f"(hi), "f"(lo));
    return d;
}
__device__ __forceinline__ uint32_t ex2h2(uint32_t x) {
    uint32_t r;
    asm("ex2.approx.f16x2 %0, %1;" : "=r"(r) : "r"(x));
    return r;
}
__device__ __forceinline__ uint32_t smem_u32(const void* p) {
    return (uint32_t)__cvta_generic_to_shared(p);
}

#define MMA_BF16(acc, a, b0v, b1v)                                         \
    asm volatile(                                                          \
        "mma.sync.aligned.m16n8k16.row.col.f32.bf16.bf16.f32 "             \
        "{%0,%1,%2,%3}, {%4,%5,%6,%7}, {%8,%9}, {%0,%1,%2,%3};"            \
        : "+f"((acc)[0]), "+f"((acc)[1]), "+f"((acc)[2]), "+f"((acc)[3])   \
        : "r"((a)[0]), "r"((a)[1]), "r"((a)[2]), "r"((a)[3]),              \
          "r"(b0v), "r"(b1v))

#define MMA_F16(acc, a, b0v, b1v)                                          \
    asm volatile(                                                          \
        "mma.sync.aligned.m16n8k16.row.col.f32.f16.f16.f32 "               \
        "{%0,%1,%2,%3}, {%4,%5,%6,%7}, {%8,%9}, {%0,%1,%2,%3};"            \
        : "+f"((acc)[0]), "+f"((acc)[1]), "+f"((acc)[2]), "+f"((acc)[3])   \
        : "r"((a)[0]), "r"((a)[1]), "r"((a)[2]), "r"((a)[3]),              \
          "r"(b0v), "r"(b1v))

#define LDSM_X4_TRANS(r0, r1, r2, r3, addr)                                \
    asm volatile(                                                          \
        "ldmatrix.sync.aligned.m8n8.x4.trans.shared.b16 "                  \
        "{%0,%1,%2,%3}, [%4];"                                             \
        : "=r"(r0), "=r"(r1), "=r"(r2), "=r"(r3) : "r"(addr))

// ----------------------------------------------------------------------------
// Shared GEMM mainloop bits (R8-validated layout)
// ----------------------------------------------------------------------------
#define A_WSTR 12
#define B_WSTR 136
#define A_WRDS (128 * A_WSTR)
#define B_WRDS (8 * B_WSTR)

// ----------------------------------------------------------------------------
// bf16 GEMM with fp32 output (+bias, +residual, ReLU) — unchanged from R8.
// ----------------------------------------------------------------------------
struct GemmArgs {
    const float* A[3];
    const float* W[3];
    const float* bias[3];
    const float* R[3];
    float*       C[3];
    int N, K;
};

template<bool RELU, bool RES>
__global__ __launch_bounds__(256, 2) void gemm_bf16(GemmArgs args)
{
    __shared__ uint32_t As[2][A_WRDS];
    __shared__ uint32_t Bs[2][B_WRDS];

    const int zi = blockIdx.z;
    const float* __restrict__ A    = args.A[zi];
    const float* __restrict__ W    = args.W[zi];
    const float* __restrict__ bias = args.bias[zi];
    const float* __restrict__ Rp   = args.R[zi];
    float*       __restrict__ C    = args.C[zi];
    const int N = args.N, K = args.K;

    const int tid  = threadIdx.x;
    const int lane = tid & 31;
    const int warp = tid >> 5;
    const int g    = lane >> 2;
    const int tg   = lane & 3;
    const int wm   = (warp >> 2) * 64;
    const int wn   = (warp & 3) * 32;
    const int bm   = blockIdx.y * 128;
    const int bn   = blockIdx.x * 128;

    const int a_row = tid >> 2;
    const int a_c4  = (tid & 3) * 4;
    const int b_p   = tid >> 5;
    const int b_c4  = (tid & 31) * 4;

    const float* Ag0 = A + (size_t)(bm + a_row)      * K + a_c4;
    const float* Ag1 = A + (size_t)(bm + a_row + 64) * K + a_c4;
    const float* Wg0 = W + (size_t)(2 * b_p)     * N + bn + b_c4;
    const float* Wg1 = W + (size_t)(2 * b_p + 1) * N + bn + b_c4;

    float acc[4][4][4];
#pragma unroll
    for (int i = 0; i < 4; i++)
#pragma unroll
        for (int j = 0; j < 4; j++)
#pragma unroll
            for (int r = 0; r < 4; r++) acc[i][j][r] = 0.f;

    float4 ra0, ra1, rb0, rb1;

#define LOADG(t) do {                                                \
        const size_t ka = (size_t)(t) * 16;                          \
        const size_t kb = (size_t)(t) * 16 * (size_t)N;              \
        ra0 = *(const float4*)(Ag0 + ka);                            \
        ra1 = *(const float4*)(Ag1 + ka);                            \
        rb0 = *(const float4*)(Wg0 + kb);                            \
        rb1 = *(const float4*)(Wg1 + kb);                            \
    } while (0)

#define STORES(buf) do {                                             \
        uint32_t* as_ = As[buf];                                     \
        uint32_t* bs_ = Bs[buf];                                     \
        uint2 aw0, aw1;                                              \
        aw0.x = packbf(ra0.x, ra0.y); aw0.y = packbf(ra0.z, ra0.w);  \
        aw1.x = packbf(ra1.x, ra1.y); aw1.y = packbf(ra1.z, ra1.w);  \
        *(uint2*)(as_ + a_row * A_WSTR + (a_c4 >> 1)) = aw0;         \
        *(uint2*)(as_ + (a_row + 64) * A_WSTR + (a_c4 >> 1)) = aw1;  \
        uint4 bw;                                                    \
        bw.x = packbf(rb0.x, rb1.x); bw.y = packbf(rb0.y, rb1.y);    \
        bw.z = packbf(rb0.z, rb1.z); bw.w = packbf(rb0.w, rb1.w);    \
        *(uint4*)(bs_ + b_p * B_WSTR + b_c4) = bw;                   \
    } while (0)

    const int NT = K >> 4;

    LOADG(0);
    STORES(0);
    __syncthreads();

    for (int t = 0; t < NT; t++) {
        const int cur = t & 1;
        if (t + 1 < NT) LOADG(t + 1);

        const uint32_t* as_ = As[cur];
        const uint32_t* bs_ = Bs[cur];

        unsigned af[4][4], bf2[4][2];
#pragma unroll
        for (int mt = 0; mt < 4; mt++) {
            const uint32_t* ap = as_ + (wm + mt * 16 + g) * A_WSTR + tg;
            af[mt][0] = ap[0];
            af[mt][1] = ap[8 * A_WSTR];
            af[mt][2] = ap[4];
            af[mt][3] = ap[8 * A_WSTR + 4];
        }
#pragma unroll
        for (int nt = 0; nt < 4; nt++) {
            const int col = wn + nt * 8 + g;
            bf2[nt][0] = bs_[tg * B_WSTR + col];
            bf2[nt][1] = bs_[(tg + 4) * B_WSTR + col];
        }
#pragma unroll
        for (int mt = 0; mt < 4; mt++)
#pragma unroll
            for (int nt = 0; nt < 4; nt++)
                MMA_BF16(acc[mt][nt], af[mt], bf2[nt][0], bf2[nt][1]);

        if (t + 1 < NT) STORES((t + 1) & 1);
        __syncthreads();
    }

#pragma unroll
    for (int mt = 0; mt < 4; mt++) {
        const int row0 = bm + wm + mt * 16 + g;
#pragma unroll
        for (int nt = 0; nt < 4; nt++) {
            const int col = bn + wn + nt * 8 + tg * 2;
            const float bv0 = bias[col], bv1 = bias[col + 1];
            float2 v0, v1;
            v0.x = acc[mt][nt][0] + bv0; v0.y = acc[mt][nt][1] + bv1;
            v1.x = acc[mt][nt][2] + bv0; v1.y = acc[mt][nt][3] + bv1;
            if (RES) {
                float2 r0 = *(const float2*)(Rp + (size_t)row0 * N + col);
                float2 r1 = *(const float2*)(Rp + (size_t)(row0 + 8) * N + col);
                v0.x += r0.x; v0.y += r0.y;
                v1.x += r1.x; v1.y += r1.y;
            }
            if (RELU) {
                v0.x = fmaxf(v0.x, 0.f); v0.y = fmaxf(v0.y, 0.f);
                v1.x = fmaxf(v1.x, 0.f); v1.y = fmaxf(v1.y, 0.f);
            }
            *(float2*)(C + (size_t)row0 * N + col)       = v0;
            *(float2*)(C + (size_t)(row0 + 8) * N + col) = v1;
        }
    }
#undef LOADG
#undef STORES
}

// ----------------------------------------------------------------------------
// bf16 GEMM with fp16 output: C16 = f16((A@W + bias) * scale).
// Used for QKV projections (scale folds attention's QSCALE into Q).
// ----------------------------------------------------------------------------
struct GemmH16Args {
    const float* A[3];
    const float* W[3];
    const float* bias[3];
    uint16_t*    C[3];
    float        scale[3];
    int N, K;
};

__global__ __launch_bounds__(256, 2) void gemm_h16(GemmH16Args args)
{
    __shared__ uint32_t As[2][A_WRDS];
    __shared__ uint32_t Bs[2][B_WRDS];

    const int zi = blockIdx.z;
    const float* __restrict__ A    = args.A[zi];
    const float* __restrict__ W    = args.W[zi];
    const float* __restrict__ bias = args.bias[zi];
    uint16_t*    __restrict__ C16  = args.C[zi];
    const float sc = args.scale[zi];
    const int N = args.N, K = args.K;

    const int tid  = threadIdx.x;
    const int lane = tid & 31;
    const int warp = tid >> 5;
    const int g    = lane >> 2;
    const int tg   = lane & 3;
    const int wm   = (warp >> 2) * 64;
    const int wn   = (warp & 3) * 32;
    const int bm   = blockIdx.y * 128;
    const int bn   = blockIdx.x * 128;

    const int a_row = tid >> 2;
    const int a_c4  = (tid & 3) * 4;
    const int b_p   = tid >> 5;
    const int b_c4  = (tid & 31) * 4;

    const float* Ag0 = A + (size_t)(bm + a_row)      * K + a_c4;
    const float* Ag1 = A + (size_t)(bm + a_row + 64) * K + a_c4;
    const float* Wg0 = W + (size_t)(2 * b_p)     * N + bn + b_c4;
    const float* Wg1 = W + (size_t)(2 * b_p + 1) * N + bn + b_c4;

    float acc[4][4][4];
#pragma unroll
    for (int i = 0; i < 4; i++)
#pragma unroll
        for (int j = 0; j < 4; j++)
#pragma unroll
            for (int r = 0; r < 4; r++) acc[i][j][r] = 0.f;

    float4 ra0, ra1, rb0, rb1;

#define LOADG(t) do {                                                \
        const size_t ka = (size_t)(t) * 16;                          \
        const size_t kb = (size_t)(t) * 16 * (size_t)N;              \
        ra0 = *(const float4*)(Ag0 + ka);                            \
        ra1 = *(const float4*)(Ag1 + ka);                            \
        rb0 = *(const float4*)(Wg0 + kb);                            \
        rb1 = *(const float4*)(Wg1 + kb);                            \
    } while (0)

#define STORES(buf) do {                                             \
        uint32_t* as_ = As[buf];                                     \
        uint32_t* bs_ = Bs[buf];                                     \
        uint2 aw0, aw1;                                              \
        aw0.x = packbf(ra0.x, ra0.y); aw0.y = packbf(ra0.z, ra0.w);  \
        aw1.x = packbf(ra1.x, ra1.y); aw1.y = packbf(ra1.z, ra1.w);  \
        *(uint2*)(as_ + a_row * A_WSTR + (a_c4 >> 1)) = aw0;         \
        *(uint2*)(as_ + (a_row + 64) * A_WSTR + (a_c4 >> 1)) = aw1;  \
        uint4 bw;                                                    \
        bw.x = packbf(rb0.x, rb1.x); bw.y = packbf(rb0.y, rb1.y);    \
        bw.z = packbf(rb0.z, rb1.z); bw.w = packbf(rb0.w, rb1.w);    \
        *(uint4*)(bs_ + b_p * B_WSTR + b_c4) = bw;                   \
    } while (0)

    const int NT = K >> 4;

    LOADG(0);
    STORES(0);
    __syncthreads();

    for (int t = 0; t < NT; t++) {
        const int cur = t & 1;
        if (t + 1 < NT) LOADG(t + 1);

        const uint32_t* as_ = As[cur];
        const uint32_t* bs_ = Bs[cur];

        unsigned af[4][4], bf2[4][2];
#pragma unroll
        for (int mt = 0; mt < 4; mt++) {
            const uint32_t* ap = as_ + (wm + mt * 16 + g) * A_WSTR + tg;
            af[mt][0] = ap[0];
            af[mt][1] = ap[8 * A_WSTR];
            af[mt][2] = ap[4];
            af[mt][3] = ap[8 * A_WSTR + 4];
        }
#pragma unroll
        for (int nt = 0; nt < 4; nt++) {
            const int col = wn + nt * 8 + g;
            bf2[nt][0] = bs_[tg * B_WSTR + col];
            bf2[nt][1] = bs_[(tg + 4) * B_WSTR + col];
        }
#pragma unroll
        for (int mt = 0; mt < 4; mt++)
#pragma unroll
            for (int nt = 0; nt < 4; nt++)
                MMA_BF16(acc[mt][nt], af[mt], bf2[nt][0], bf2[nt][1]);

        if (t + 1 < NT) STORES((t + 1) & 1);
        __syncthreads();
    }

#pragma unroll
    for (int mt = 0; mt < 4; mt++) {
        const int row0 = bm + wm + mt * 16 + g;
#pragma unroll
        for (int nt = 0; nt < 4; nt++) {
            const int col = bn + wn + nt * 8 + tg * 2;
            const float bv0 = bias[col], bv1 = bias[col + 1];
            const uint32_t w0 = packh((acc[mt][nt][0] + bv0) * sc,
                                      (acc[mt][nt][1] + bv1) * sc);
            const uint32_t w1 = packh((acc[mt][nt][2] + bv0) * sc,
                                      (acc[mt][nt][3] + bv1) * sc);
            *(uint32_t*)(C16 + (size_t)row0 * N + col)       = w0;
            *(uint32_t*)(C16 + (size_t)(row0 + 8) * N + col) = w1;
        }
    }
#undef LOADG
#undef STORES
}

// ----------------------------------------------------------------------------
// fp16 flash attention (R12-validated), now reading pre-converted fp16 QKV.
// Staging = pure uint4 copies; Q already scaled by QSCALE.
// ----------------------------------------------------------------------------
#define HSTR 72            // halves per smem row (64 + 8 pad)

template<bool CAUSAL>
__global__ __launch_bounds__(128) void attn_fp16(
    const uint16_t* __restrict__ Q, const uint16_t* __restrict__ K,
    const uint16_t* __restrict__ V, float* __restrict__ O)
{
    __shared__ __align__(16) uint16_t sQ[64 * HSTR];
    __shared__ __align__(16) uint16_t sK[64 * HSTR];
    __shared__ __align__(16) uint16_t sV[64 * HSTR];
    uint32_t* sQw = (uint32_t*)sQ;     // word stride 36
    uint32_t* sKw = (uint32_t*)sK;

    const int b  = blockIdx.z;
    const int h  = blockIdx.y;
    const int q0 = blockIdx.x * 64;
    const int tid  = threadIdx.x;
    const int lane = tid & 31;
    const int w    = tid >> 5;
    const int g    = lane >> 2;
    const int tg   = lane & 3;
    const size_t hoff = ((size_t)(b * NHEADS + h)) * SEQ * HDIM;
    const uint32_t sVbase = smem_u32(sV);

    // ---- stage Q: 64 rows x 8 uint4 = 512 copies, 4/thread ----
#pragma unroll
    for (int i = 0; i < 4; i++) {
        const int idx = tid + i * 128;
        const int row = idx >> 3;
        const int c8  = idx & 7;           // 8-half group
        uint4 qv = *(const uint4*)(Q + hoff + (size_t)(q0 + row) * HDIM + c8 * 8);
        *(uint4*)(sQw + row * 36 + c8 * 4) = qv;
    }
    __syncthreads();

    // ---- Q fragments (register resident); rows = w*16 + {g, g+8} ----
    uint32_t aQ[4][4];
#pragma unroll
    for (int kk = 0; kk < 4; kk++) {
        const uint32_t* qb = sQw + (w * 16 + g) * 36 + kk * 8 + tg;
        aQ[kk][0] = qb[0];
        aQ[kk][1] = qb[8 * 36];
        aQ[kk][2] = qb[4];
        aQ[kk][3] = qb[8 * 36 + 4];
    }

    float cO[8][4];
#pragma unroll
    for (int nt = 0; nt < 8; nt++)
#pragma unroll
        for (int r = 0; r < 4; r++) cO[nt][r] = 0.f;
    float lrow[2] = { 0.f, 0.f };

    const int ntiles = CAUSAL ? (q0 / 64 + 1) : (SEQ / 64);

    for (int t = 0; t < ntiles; t++) {
        const int j0 = t * 64;
        __syncthreads();
        // ---- stage K, V: uint4 copies ----
#pragma unroll
        for (int i = 0; i < 4; i++) {
            const int idx = tid + i * 128;
            const int row = idx >> 3;
            const int c8  = idx & 7;
            const size_t gaddr = hoff + (size_t)(j0 + row) * HDIM + c8 * 8;
            uint4 kv = *(const uint4*)(K + gaddr);
            *(uint4*)(sKw + row * 36 + c8 * 4) = kv;
            uint4 vv = *(const uint4*)(V + gaddr);
            *(uint4*)((uint32_t*)sV + row * 36 + c8 * 4) = vv;
        }
        __syncthreads();

        // ---- S = Q @ K^T (log2 domain; scale pre-folded into Q) ----
        float cS[8][4];
#pragma unroll
        for (int nt = 0; nt < 8; nt++)
#pragma unroll
            for (int r = 0; r < 4; r++) cS[nt][r] = 0.f;

#pragma unroll
        for (int kk = 0; kk < 4; kk++)
#pragma unroll
            for (int nt = 0; nt < 8; nt++) {
                const uint32_t* kp = sKw + (nt * 8 + g) * 36 + kk * 8 + tg;
                MMA_F16(cS[nt], aQ[kk], kp[0], kp[4]);
            }

        // ---- causal mask (diagonal tile only) ----
        if (CAUSAL && t == ntiles - 1) {
            const int rbase = q0 + w * 16 + g;
#pragma unroll
            for (int nt = 0; nt < 8; nt++) {
                const int c0 = j0 + nt * 8 + tg * 2;
                if (c0     > rbase)     cS[nt][0] = -1e30f;
                if (c0 + 1 > rbase)     cS[nt][1] = -1e30f;
                if (c0     > rbase + 8) cS[nt][2] = -1e30f;
                if (c0 + 1 > rbase + 8) cS[nt][3] = -1e30f;
            }
        }

        // ---- p = 2^S, packed f16x2 (these ARE the PV A-frag words) ----
        uint32_t plo[8], phi[8];
#pragma unroll
        for (int nt = 0; nt < 8; nt++) {
            plo[nt] = ex2h2(packh(cS[nt][0], cS[nt][1]));
            phi[nt] = ex2h2(packh(cS[nt][2], cS[nt][3]));
        }

        uint32_t aP[4][4];
#pragma unroll
        for (int kk = 0; kk < 4; kk++) {
            aP[kk][0] = plo[2 * kk];
            aP[kk][1] = phi[2 * kk];
            aP[kk][2] = plo[2 * kk + 1];
            aP[kk][3] = phi[2 * kk + 1];
        }

        // ---- row sums via mma with B = ones (fp32 accumulate) ----
        {
            float cSum[4] = { 0.f, 0.f, 0.f, 0.f };
#pragma unroll
            for (int kk = 0; kk < 4; kk++)
                MMA_F16(cSum, aP[kk], 0x3C003C00u, 0x3C003C00u);
            lrow[0] += cSum[0];
            lrow[1] += cSum[2];
        }

        // ---- O += P @ V : V B-frags via ldmatrix.x4.trans ----
#pragma unroll
        for (int kk = 0; kk < 4; kk++)
#pragma unroll
            for (int np = 0; np < 4; np++) {
                const int mat = lane >> 3;
                const int r   = lane & 7;
                const int key = kk * 16 + (mat & 1) * 8 + r;
                const int dcl = np * 16 + (mat >> 1) * 8;
                const uint32_t addr = sVbase + (uint32_t)(key * HSTR + dcl) * 2;
                uint32_t v0, v1, v2, v3;
                LDSM_X4_TRANS(v0, v1, v2, v3, addr);
                MMA_F16(cO[2 * np],     aP[kk], v0, v1);
                MMA_F16(cO[2 * np + 1], aP[kk], v2, v3);
            }
    }

    // ---- epilogue: normalize and store (folds head transpose) ----
    const float inv0 = 1.f / lrow[0];
    const float inv1 = 1.f / lrow[1];
    const int r0 = q0 + w * 16 + g;
    float* o0p = O + (size_t)(b * SEQ + r0) * DMODEL + h * HDIM;
    float* o1p = O + (size_t)(b * SEQ + r0 + 8) * DMODEL + h * HDIM;
#pragma unroll
    for (int nt = 0; nt < 8; nt++) {
        const int c = nt * 8 + tg * 2;
        float2 v0, v1;
        v0.x = cO[nt][0] * inv0; v0.y = cO[nt][1] * inv0;
        v1.x = cO[nt][2] * inv1; v1.y = cO[nt][3] * inv1;
        *(float2*)(o0p + c) = v0;
        *(float2*)(o1p + c) = v1;
    }
}

// ----------------------------------------------------------------------------
// LayerNorm (unchanged)
// ----------------------------------------------------------------------------
__global__ __launch_bounds__(256) void ln_kernel(
    const float* __restrict__ X, const float* __restrict__ g,
    const float* __restrict__ bb, float* __restrict__ Y)
{
    __shared__ float red[16];
    const int row = blockIdx.x;
    const int tid = threadIdx.x;
    const float4 xv = *(const float4*)(X + (size_t)row * DMODEL + tid * 4);

    float s  = xv.x + xv.y + xv.z + xv.w;
    float sq = xv.x*xv.x + xv.y*xv.y + xv.z*xv.z + xv.w*xv.w;
#pragma unroll
    for (int off = 16; off > 0; off >>= 1) {
        s  += __shfl_xor_sync(0xffffffffu, s,  off);
        sq += __shfl_xor_sync(0xffffffffu, sq, off);
    }
    const int warp = tid >> 5, lane = tid & 31;
    if (lane == 0) { red[warp] = s; red[warp + 8] = sq; }
    __syncthreads();
    if (warp == 0) {
        float a = (lane < 8) ? red[lane] : 0.f;
        float c = (lane < 8) ? red[lane + 8] : 0.f;
#pragma unroll
        for (int off = 4; off > 0; off >>= 1) {
            a += __shfl_xor_sync(0xffffffffu, a, off);
            c += __shfl_xor_sync(0xffffffffu, c, off);
        }
        if (lane == 0) { red[0] = a; red[1] = c; }
    }
    __syncthreads();
    const float mu  = red[0] * (1.f / DMODEL);
    const float var = red[1] * (1.f / DMODEL) - mu * mu;
    const float rstd = rsqrtf(var + LN_EPS);

    const float4 gv = *(const float4*)(g  + tid * 4);
    const float4 bv = *(const float4*)(bb + tid * 4);
    float4 yv;
    yv.x = (xv.x - mu) * rstd * gv.x + bv.x;
    yv.y = (xv.y - mu) * rstd * gv.y + bv.y;
    yv.z = (xv.z - mu) * rstd * gv.z + bv.z;
    yv.w = (xv.w - mu) * rstd * gv.w + bv.w;
    *(float4*)(Y + (size_t)row * DMODEL + tid * 4) = yv;
}

// ----------------------------------------------------------------------------
// Launch
// ----------------------------------------------------------------------------
extern "C" void kernel_launch(void* const* d_in, const int* in_sizes, int n_in,
                              void* d_out, int out_size)
{
    const float* x    = (const float*)d_in[0];
    const float* enc  = (const float*)d_in[1];
    const float* s_wq = (const float*)d_in[2];  const float* s_bq = (const float*)d_in[3];
    const float* s_wk = (const float*)d_in[4];  const float* s_bk = (const float*)d_in[5];
    const float* s_wv = (const float*)d_in[6];  const float* s_bv = (const float*)d_in[7];
    const float* s_wo = (const float*)d_in[8];  const float* s_bo = (const float*)d_in[9];
    const float* c_wq = (const float*)d_in[10]; const float* c_bq = (const float*)d_in[11];
    const float* c_wk = (const float*)d_in[12]; const float* c_bk = (const float*)d_in[13];
    const float* c_wv = (const float*)d_in[14]; const float* c_bv = (const float*)d_in[15];
    const float* c_wo = (const float*)d_in[16]; const float* c_bo = (const float*)d_in[17];
    const float* f_w1 = (const float*)d_in[18]; const float* f_b1 = (const float*)d_in[19];
    const float* f_w2 = (const float*)d_in[20]; const float* f_b2 = (const float*)d_in[21];
    const float* ln1g = (const float*)d_in[22]; const float* ln1b = (const float*)d_in[23];
    const float* ln2g = (const float*)d_in[24]; const float* ln2b = (const float*)d_in[25];
    const float* ln3g = (const float*)d_in[26]; const float* ln3b = (const float*)d_in[27];
    float* out = (float*)d_out;

    uint16_t *q, *k, *v;
    float *attn, *tmp, *y1, *y2, *ffn;
    cudaGetSymbolAddress((void**)&q,    h_q);
    cudaGetSymbolAddress((void**)&k,    h_k);
    cudaGetSymbolAddress((void**)&v,    h_v);
    cudaGetSymbolAddress((void**)&attn, g_attn);
    cudaGetSymbolAddress((void**)&tmp,  g_tmp);
    cudaGetSymbolAddress((void**)&y1,   g_y1);
    cudaGetSymbolAddress((void**)&y2,   g_y2);
    cudaGetSymbolAddress((void**)&ffn,  g_ffn);

    const dim3 blk(256);
    const dim3 ablk(128);
    const dim3 gatt(SEQ / 64, NHEADS, BATCH);
    const dim3 gln(TOK);

    GemmArgs ga;
    GemmH16Args gh;

    // ---- self attention: fused QKV projection -> fp16 (z=3) ----
    gh = GemmH16Args{};
    gh.A[0] = x;    gh.A[1] = x;    gh.A[2] = x;
    gh.W[0] = s_wq; gh.W[1] = s_wk; gh.W[2] = s_wv;
    gh.bias[0] = s_bq; gh.bias[1] = s_bk; gh.bias[2] = s_bv;
    gh.C[0] = q; gh.C[1] = k; gh.C[2] = v;
    gh.scale[0] = QSCALE; gh.scale[1] = 1.f; gh.scale[2] = 1.f;
    gh.N = DMODEL; gh.K = DMODEL;
    gemm_h16<<<dim3(DMODEL/128, TOK/128, 3), blk>>>(gh);

    attn_fp16<true><<<gatt, ablk>>>(q, k, v, attn);

    ga = GemmArgs{};
    ga.A[0] = attn; ga.W[0] = s_wo; ga.bias[0] = s_bo; ga.R[0] = x; ga.C[0] = tmp;
    ga.N = DMODEL; ga.K = DMODEL;
    gemm_bf16<false,true><<<dim3(DMODEL/128, TOK/128, 1), blk>>>(ga);
    ln_kernel<<<gln, blk>>>(tmp, ln1g, ln1b, y1);

    // ---- cross attention: fused Q(y1) + K,V(enc) projection -> fp16 ----
    gh.A[0] = y1;   gh.A[1] = enc;  gh.A[2] = enc;
    gh.W[0] = c_wq; gh.W[1] = c_wk; gh.W[2] = c_wv;
    gh.bias[0] = c_bq; gh.bias[1] = c_bk; gh.bias[2] = c_bv;
    gh.C[0] = q; gh.C[1] = k; gh.C[2] = v;
    gemm_h16<<<dim3(DMODEL/128, TOK/128, 3), blk>>>(gh);

    attn_fp16<false><<<gatt, ablk>>>(q, k, v, attn);

    ga.A[0] = attn; ga.W[0] = c_wo; ga.bias[0] = c_bo; ga.R[0] = y1; ga.C[0] = tmp;
    gemm_bf16<false,true><<<dim3(DMODEL/128, TOK/128, 1), blk>>>(ga);
    ln_kernel<<<gln, blk>>>(tmp, ln2g, ln2b, y2);

    // ---- FFN ----
    ga.A[0] = y2; ga.W[0] = f_w1; ga.bias[0] = f_b1; ga.R[0] = x; ga.C[0] = ffn;
    ga.N = DFF; ga.K = DMODEL;
    gemm_bf16<true,false><<<dim3(DFF/128, TOK/128, 1), blk>>>(ga);

    ga.A[0] = ffn; ga.W[0] = f_w2; ga.bias[0] = f_b2; ga.R[0] = y2; ga.C[0] = tmp;
    ga.N = DMODEL; ga.K = DFF;
    gemm_bf16<false,true><<<dim3(DMODEL/128, TOK/128, 1), blk>>>(ga);
    ln_kernel<<<gln, blk>>>(tmp, ln3g, ln3b, out);
}